// round 1
// baseline (speedup 1.0000x reference)
#include <cuda_runtime.h>

#define NN 200000
#define NE 1000000
#define NG 4096

// ------------------------- scratch (static device globals; no allocs) ------
static __device__ float g_deg[NN];
static __device__ float g_dis[NN];
static __device__ float g_invdeg[NN];
static __device__ float g_x12[NN * 12];
static __device__ float g_agg12[NN * 12];
static __device__ float g_agg[NN * 64];
static __device__ float g_h[NN * 64];
static __device__ float g_pooled[NG * 64];
static __device__ float g_cnt[NG];

__device__ __forceinline__ void red_add_v4(float* p, float4 v) {
    asm volatile("red.global.add.v4.f32 [%0], {%1,%2,%3,%4};"
                 :: "l"(p), "f"(v.x), "f"(v.y), "f"(v.z), "f"(v.w)
                 : "memory");
}

// ------------------------- init: deg=1 (self loop), pooled=0, cnt=0 --------
__global__ void k_init(int n) {
    int i = blockIdx.x * blockDim.x + threadIdx.x;
    if (i < n) g_deg[i] = 1.0f;
    if (i < NG * 64) g_pooled[i] = 0.0f;
    if (i < NG) g_cnt[i] = 0.0f;
}

// ------------------------- degree accumulation ------------------------------
__global__ void k_deg(const int* __restrict__ dst, int e) {
    int i = blockIdx.x * blockDim.x + threadIdx.x;
    if (i < e) atomicAdd(&g_deg[dst[i]], 1.0f);
}

// --------- per-node: dis, invdeg, padded x copy, layer-1 agg init, counts ---
__global__ void k_node(const float* __restrict__ x, const int* __restrict__ batch, int n) {
    int i = blockIdx.x * blockDim.x + threadIdx.x;
    if (i >= n) return;
    float d = g_deg[i];
    float id = 1.0f / d;
    g_dis[i] = rsqrtf(d);
    g_invdeg[i] = id;
#pragma unroll
    for (int c = 0; c < 11; c++) {
        float v = x[i * 11 + c];
        g_x12[i * 12 + c] = v;
        g_agg12[i * 12 + c] = v * id;   // self-loop message: x * dis^2 = x/deg
    }
    g_x12[i * 12 + 11] = 0.0f;
    g_agg12[i * 12 + 11] = 0.0f;
    atomicAdd(&g_cnt[batch[i]], 1.0f);
}

// ---------------- layer-1 scatter: 12-float (padded) messages ---------------
__global__ void k_scatter12(const int* __restrict__ src, const int* __restrict__ dst, int e) {
    int t = blockIdx.x * blockDim.x + threadIdx.x;
    if (t >= e * 3) return;
    int eid = t / 3;
    int c = (t - eid * 3) * 4;
    int s = src[eid];
    int d = dst[eid];
    float nrm = g_dis[s] * g_dis[d];
    float4 v = *(const float4*)&g_x12[s * 12 + c];
    v.x *= nrm; v.y *= nrm; v.z *= nrm; v.w *= nrm;
    red_add_v4(&g_agg12[d * 12 + c], v);
}

// ---------------- 64-dim scatter: 16 lanes/edge, float4 gather + v4 red -----
__global__ void k_scatter64(const float* __restrict__ H,
                            const int* __restrict__ src, const int* __restrict__ dst, int e) {
    int gid = blockIdx.x * blockDim.x + threadIdx.x;
    int eid = gid >> 4;
    if (eid >= e) return;
    int c = (gid & 15) * 4;
    int s = src[eid];
    int d = dst[eid];
    float nrm = g_dis[s] * g_dis[d];
    float4 v = *(const float4*)&H[s * 64 + c];
    v.x *= nrm; v.y *= nrm; v.z *= nrm; v.w *= nrm;
    red_add_v4(&g_agg[d * 64 + c], v);
}

// ---------------- tiled GEMM: [n,K] x [K,64] + bias, fused epilogues --------
// 64-node tile, 128 threads, each thread computes 4 nodes x 8 outputs.
template <int K, int KREAL, int ASTR, bool RELU, bool HOUT, bool SELF, bool POOL>
__global__ void __launch_bounds__(128)
k_gemm(const float* __restrict__ A, const float* __restrict__ W,
       const float* __restrict__ bias, float* __restrict__ Hout,
       float* __restrict__ aggInit, const int* __restrict__ batch, int n) {
    __shared__ float Am[64 * (K + 1)];
    __shared__ float Ws[K * 64];
    __shared__ float Bs[64];
    const int t = threadIdx.x;
    const int base = blockIdx.x * 64;

    for (int i = t; i < K * 64; i += 128) Ws[i] = (i < KREAL * 64) ? W[i] : 0.0f;
    if (t < 64) Bs[t] = bias[t];

    // stage A tile (row-major, pad stride K+1 to break read conflicts)
    for (int idx = t; idx < 64 * (K / 4); idx += 128) {
        int m = idx / (K / 4);
        int q = idx - m * (K / 4);
        float4 v = make_float4(0.f, 0.f, 0.f, 0.f);
        int g = base + m;
        if (g < n) v = *(const float4*)&A[(size_t)g * ASTR + q * 4];
        Am[m * (K + 1) + q * 4 + 0] = v.x;
        Am[m * (K + 1) + q * 4 + 1] = v.y;
        Am[m * (K + 1) + q * 4 + 2] = v.z;
        Am[m * (K + 1) + q * 4 + 3] = v.w;
    }
    __syncthreads();

    const int m0 = (t & 15) * 4;
    const int j0 = (t >> 4) * 8;
    float acc[32];
#pragma unroll
    for (int i = 0; i < 32; i++) acc[i] = 0.0f;

#pragma unroll 4
    for (int k = 0; k < K; k++) {
        float4 w0 = *(const float4*)&Ws[k * 64 + j0];
        float4 w1 = *(const float4*)&Ws[k * 64 + j0 + 4];
        float wv[8] = {w0.x, w0.y, w0.z, w0.w, w1.x, w1.y, w1.z, w1.w};
#pragma unroll
        for (int i = 0; i < 4; i++) {
            float a = Am[(m0 + i) * (K + 1) + k];
#pragma unroll
            for (int j = 0; j < 8; j++) acc[i * 8 + j] += a * wv[j];
        }
    }

#pragma unroll
    for (int i = 0; i < 4; i++) {
        int g = base + m0 + i;
        if (g >= n) continue;
        float o[8];
#pragma unroll
        for (int j = 0; j < 8; j++) {
            o[j] = acc[i * 8 + j] + Bs[j0 + j];
            if (RELU) o[j] = fmaxf(o[j], 0.0f);
        }
        float4 o0 = make_float4(o[0], o[1], o[2], o[3]);
        float4 o1 = make_float4(o[4], o[5], o[6], o[7]);
        if (HOUT) {
            *(float4*)&Hout[g * 64 + j0] = o0;
            *(float4*)&Hout[g * 64 + j0 + 4] = o1;
        }
        if (SELF) {  // next layer's self-loop message: h / deg (init of agg buffer)
            float id = g_invdeg[g];
            *(float4*)&aggInit[g * 64 + j0] =
                make_float4(o0.x * id, o0.y * id, o0.z * id, o0.w * id);
            *(float4*)&aggInit[g * 64 + j0 + 4] =
                make_float4(o1.x * id, o1.y * id, o1.z * id, o1.w * id);
        }
        if (POOL) {  // layer 3: reduce h3 straight into pooled sums
            int b = batch[g];
            red_add_v4(&g_pooled[b * 64 + j0], o0);
            red_add_v4(&g_pooled[b * 64 + j0 + 4], o1);
        }
    }
}

// ---------------- final: out[g] = (pooled/cnt) . lin_w + lin_b --------------
__global__ void k_final(const float* __restrict__ lw, const float* __restrict__ lb,
                        float* __restrict__ out, int ng) {
    int g = blockIdx.x * (blockDim.x / 32) + (threadIdx.x >> 5);
    int l = threadIdx.x & 31;
    if (g >= ng) return;
    float v = g_pooled[g * 64 + l] * lw[l] + g_pooled[g * 64 + 32 + l] * lw[32 + l];
#pragma unroll
    for (int o = 16; o > 0; o >>= 1) v += __shfl_down_sync(0xFFFFFFFFu, v, o);
    if (l == 0) out[g] = v / fmaxf(g_cnt[g], 1.0f) + lb[0];
}

// ---------------------------------------------------------------------------
template <class T>
static float* sym_addr(const T& sym) {
    void* p = nullptr;
    cudaGetSymbolAddress(&p, sym);
    return (float*)p;
}

extern "C" void kernel_launch(void* const* d_in, const int* in_sizes, int n_in,
                              void* d_out, int out_size) {
    const float* x  = (const float*)d_in[0];
    const int* ei   = (const int*)d_in[1];
    const int* batch = (const int*)d_in[2];
    const float* W1 = (const float*)d_in[3];
    const float* b1 = (const float*)d_in[4];
    const float* W2 = (const float*)d_in[5];
    const float* b2 = (const float*)d_in[6];
    const float* W3 = (const float*)d_in[7];
    const float* b3 = (const float*)d_in[8];
    const float* lw = (const float*)d_in[9];
    const float* lb = (const float*)d_in[10];
    float* out = (float*)d_out;

    int n = in_sizes[0] / 11;
    int e = in_sizes[1] / 2;
    int ng = out_size;
    const int* src = ei;
    const int* dst = ei + e;

    float* p_agg12 = sym_addr(g_agg12);
    float* p_agg   = sym_addr(g_agg);
    float* p_h     = sym_addr(g_h);

    int initN = (NG * 64 > n) ? NG * 64 : n;
    k_init<<<(initN + 255) / 256, 256>>>(n);
    k_deg<<<(e + 255) / 256, 256>>>(dst, e);
    k_node<<<(n + 255) / 256, 256>>>(x, batch, n);

    // layer 1: aggregate 11-dim raw features, then GEMM (linearity commute)
    k_scatter12<<<(e * 3 + 255) / 256, 256>>>(src, dst, e);
    int gb = (n + 63) / 64;
    k_gemm<12, 11, 12, true, true, true, false><<<gb, 128>>>(
        p_agg12, W1, b1, p_h, p_agg, nullptr, n);

    // layer 2
    k_scatter64<<<(e * 16 + 255) / 256, 256>>>(p_h, src, dst, e);
    k_gemm<64, 64, 64, true, true, true, false><<<gb, 128>>>(
        p_agg, W2, b2, p_h, p_agg, nullptr, n);

    // layer 3 (no relu, fused pooling reduce; h3 never materialized)
    k_scatter64<<<(e * 16 + 255) / 256, 256>>>(p_h, src, dst, e);
    k_gemm<64, 64, 64, false, false, false, true><<<gb, 128>>>(
        p_agg, W3, b3, nullptr, nullptr, batch, n);

    k_final<<<(ng + 7) / 8, 256>>>(lw, lb, out, ng);
}

// round 2
// speedup vs baseline: 1.3169x; 1.3169x over previous
#include <cuda_runtime.h>

#define NN 200000
#define NE 1000000
#define NG 4096

// ------------------------- scratch (static device globals) -----------------
static __device__ int   g_degi[NN];
static __device__ int   g_off[NN + 1];
static __device__ int   g_cursor[NN];
static __device__ int   g_csrc[NE + 1];
static __device__ int   g_bsum[256];
static __device__ int   g_boff[256];
static __device__ float g_dis[NN];
static __device__ float g_invdeg[NN];
static __device__ float g_x16[NN * 16];
static __device__ float g_agg16[NN * 16];
static __device__ float g_agg[NN * 64];
static __device__ float g_h[NN * 64];
static __device__ float g_pooled[NG * 64];
static __device__ float g_cnt[NG];

__device__ __forceinline__ void red_add_v4(float* p, float4 v) {
    asm volatile("red.global.add.v4.f32 [%0], {%1,%2,%3,%4};"
                 :: "l"(p), "f"(v.x), "f"(v.y), "f"(v.z), "f"(v.w)
                 : "memory");
}

// packed f32x2 FMA (Blackwell): acc = a*b + acc, two lanes per op
__device__ __forceinline__ void ffma2(float2& acc, float2 a, float2 b) {
    asm("fma.rn.f32x2 %0, %1, %2, %0;"
        : "+l"(*reinterpret_cast<unsigned long long*>(&acc))
        : "l"(*reinterpret_cast<const unsigned long long*>(&a)),
          "l"(*reinterpret_cast<const unsigned long long*>(&b)));
}

// ------------------------- init ---------------------------------------------
__global__ void k_init(int n) {
    int i = blockIdx.x * blockDim.x + threadIdx.x;
    if (i < n) g_degi[i] = 0;
    if (i < NG * 64) g_pooled[i] = 0.0f;
    if (i < NG) g_cnt[i] = 0.0f;
}

// ------------------------- degree histogram (int) ---------------------------
__global__ void k_deg(const int* __restrict__ dst, int e) {
    int i = blockIdx.x * blockDim.x + threadIdx.x;
    if (i < e) atomicAdd(&g_degi[dst[i]], 1);
}

// ------------------------- 3-phase exclusive scan of g_degi -----------------
__global__ void k_scanA(int n) {
    __shared__ int ws[8];
    int b = blockIdx.x, t = threadIdx.x;
    int base = b * 1024;
    int sum = 0;
    for (int i = t; i < 1024; i += 256) {
        int g = base + i;
        if (g < n) sum += g_degi[g];
    }
#pragma unroll
    for (int o = 16; o; o >>= 1) sum += __shfl_down_sync(~0u, sum, o);
    if ((t & 31) == 0) ws[t >> 5] = sum;
    __syncthreads();
    if (t < 8) {
        int v = ws[t];
#pragma unroll
        for (int o = 4; o; o >>= 1) v += __shfl_down_sync(0xFFu, v, o);
        if (t == 0) g_bsum[b] = v;
    }
}

__global__ void k_scanB(int nb) {
    __shared__ int ws[8];
    int t = threadIdx.x;
    int v = (t < nb) ? g_bsum[t] : 0;
    int inc = v;
#pragma unroll
    for (int o = 1; o < 32; o <<= 1) {
        int u = __shfl_up_sync(~0u, inc, o);
        if ((t & 31) >= o) inc += u;
    }
    if ((t & 31) == 31) ws[t >> 5] = inc;
    __syncthreads();
    if (t < 8) {
        int w = ws[t];
#pragma unroll
        for (int o = 1; o < 8; o <<= 1) {
            int u = __shfl_up_sync(0xFFu, w, o);
            if (t >= o) w += u;
        }
        ws[t] = w;
    }
    __syncthreads();
    int excl = inc - v + ((t >= 32) ? ws[(t >> 5) - 1] : 0);
    g_boff[t] = excl;
}

// re-scan chunk, emit offsets + cursor + dis/invdeg (deg includes self loop)
__global__ void k_scanC(int n) {
    __shared__ int ws[8];
    int b = blockIdx.x, t = threadIdx.x;
    int base = b * 1024 + t * 4;
    int d[4];
#pragma unroll
    for (int i = 0; i < 4; i++) {
        int g = base + i;
        d[i] = (g < n) ? g_degi[g] : 0;
    }
    int tot = d[0] + d[1] + d[2] + d[3];
    int inc = tot;
#pragma unroll
    for (int o = 1; o < 32; o <<= 1) {
        int u = __shfl_up_sync(~0u, inc, o);
        if ((t & 31) >= o) inc += u;
    }
    if ((t & 31) == 31) ws[t >> 5] = inc;
    __syncthreads();
    if (t < 8) {
        int w = ws[t];
#pragma unroll
        for (int o = 1; o < 8; o <<= 1) {
            int u = __shfl_up_sync(0xFFu, w, o);
            if (t >= o) w += u;
        }
        ws[t] = w;
    }
    __syncthreads();
    int off = inc - tot + ((t >= 32) ? ws[(t >> 5) - 1] : 0) + g_boff[b];
#pragma unroll
    for (int i = 0; i < 4; i++) {
        int g = base + i;
        if (g < n) {
            g_off[g] = off;
            g_cursor[g] = off;
            float degf = (float)(d[i] + 1);
            g_dis[g] = rsqrtf(degf);
            g_invdeg[g] = 1.0f / degf;
            if (g == n - 1) g_off[n] = off + d[i];
            off += d[i];
        }
    }
}

// ------------------------- CSR fill -----------------------------------------
__global__ void k_fill(const int* __restrict__ src, const int* __restrict__ dst, int e) {
    int i = blockIdx.x * blockDim.x + threadIdx.x;
    if (i >= e) return;
    int p = atomicAdd(&g_cursor[dst[i]], 1);
    g_csrc[p] = src[i];
}

// --------- per-node: padded x copy + graph counts ----------------------------
__global__ void k_node(const float* __restrict__ x, const int* __restrict__ batch, int n) {
    int i = blockIdx.x * blockDim.x + threadIdx.x;
    if (i >= n) return;
    float v[16];
#pragma unroll
    for (int c = 0; c < 11; c++) v[c] = x[i * 11 + c];
#pragma unroll
    for (int c = 11; c < 16; c++) v[c] = 0.0f;
#pragma unroll
    for (int q = 0; q < 4; q++)
        *(float4*)&g_x16[i * 16 + q * 4] = make_float4(v[q*4], v[q*4+1], v[q*4+2], v[q*4+3]);
    atomicAdd(&g_cnt[batch[i]], 1.0f);
}

// ---------------- pull aggregation, 16-dim (layer 1): 4 lanes/node ----------
__global__ void k_pull16(int n) {
    int node = blockIdx.x * 64 + (threadIdx.x >> 2);
    int lane = threadIdx.x & 3;
    if (node >= n) return;
    int s0 = g_off[node], s1 = g_off[node + 1];
    float dD = g_dis[node];
    float id = g_invdeg[node];
    float4 acc = *(const float4*)&g_x16[node * 16 + lane * 4];
    acc.x *= id; acc.y *= id; acc.z *= id; acc.w *= id;
    int sA = (s0 < s1) ? g_csrc[s0] : 0;
    float dA = g_dis[sA];
    for (int k = s0; k < s1; k++) {
        int kn = k + 1;
        int sB = (kn < s1) ? g_csrc[kn] : 0;
        float dB = g_dis[sB];
        float nrm = dA * dD;
        float4 v = *(const float4*)&g_x16[sA * 16 + lane * 4];
        acc.x += v.x * nrm; acc.y += v.y * nrm; acc.z += v.z * nrm; acc.w += v.w * nrm;
        sA = sB; dA = dB;
    }
    *(float4*)&g_agg16[node * 16 + lane * 4] = acc;
}

// ---------------- pull aggregation, 64-dim: 16 lanes/node --------------------
__global__ void k_pull64(const float* __restrict__ H, float* __restrict__ AGG, int n) {
    int node = blockIdx.x * 16 + (threadIdx.x >> 4);
    int lane = threadIdx.x & 15;
    if (node >= n) return;
    int s0 = g_off[node], s1 = g_off[node + 1];
    float dD = g_dis[node];
    float id = g_invdeg[node];
    float4 acc = *(const float4*)&H[node * 64 + lane * 4];
    acc.x *= id; acc.y *= id; acc.z *= id; acc.w *= id;
    int sA = (s0 < s1) ? g_csrc[s0] : 0;
    float dA = g_dis[sA];
    for (int k = s0; k < s1; k++) {
        int kn = k + 1;
        int sB = (kn < s1) ? g_csrc[kn] : 0;
        float dB = g_dis[sB];
        float nrm = dA * dD;
        float4 v = *(const float4*)&H[sA * 64 + lane * 4];
        acc.x += v.x * nrm; acc.y += v.y * nrm; acc.z += v.z * nrm; acc.w += v.w * nrm;
        sA = sB; dA = dB;
    }
    *(float4*)&AGG[node * 64 + lane * 4] = acc;
}

// ---------------- tiled GEMM [n,K]x[K,64]+bias, f32x2 packed FMA -------------
// 64-node tile, 128 threads, 4 nodes x 8 outs per thread, k-major smem A.
template <int K, int KREAL, int ASTR, bool RELU, bool HOUT, bool POOL>
__global__ void __launch_bounds__(128)
k_gemm(const float* __restrict__ A, const float* __restrict__ W,
       const float* __restrict__ bias, float* __restrict__ Hout,
       const int* __restrict__ batch, int n) {
    __shared__ float Am[K * 72];
    __shared__ float Ws[K * 64];
    __shared__ float Bs[64];
    const int t = threadIdx.x;
    const int base = blockIdx.x * 64;

    for (int i = t; i < K * 64; i += 128) Ws[i] = (i < KREAL * 64) ? W[i] : 0.0f;
    if (t < 64) Bs[t] = bias[t];

    // stage A tile transposed to k-major (stride 72 -> conflict-free LDS.128)
    for (int idx = t; idx < 64 * (K / 4); idx += 128) {
        int m = idx & 63;
        int q = idx >> 6;
        float4 v = make_float4(0.f, 0.f, 0.f, 0.f);
        int g = base + m;
        if (g < n) v = *(const float4*)&A[(size_t)g * ASTR + q * 4];
        Am[(4 * q + 0) * 72 + m] = v.x;
        Am[(4 * q + 1) * 72 + m] = v.y;
        Am[(4 * q + 2) * 72 + m] = v.z;
        Am[(4 * q + 3) * 72 + m] = v.w;
    }
    __syncthreads();

    const int m0 = (t & 15) * 4;
    const int j0 = (t >> 4) * 8;
    float2 acc[4][4];
#pragma unroll
    for (int i = 0; i < 4; i++)
#pragma unroll
        for (int p = 0; p < 4; p++) acc[i][p] = make_float2(0.f, 0.f);

#pragma unroll 8
    for (int k = 0; k < K; k++) {
        float4 a4 = *(const float4*)&Am[k * 72 + m0];
        float4 w0 = *(const float4*)&Ws[k * 64 + j0];
        float4 w1 = *(const float4*)&Ws[k * 64 + j0 + 4];
        float2 wp[4] = {{w0.x, w0.y}, {w0.z, w0.w}, {w1.x, w1.y}, {w1.z, w1.w}};
        float a[4] = {a4.x, a4.y, a4.z, a4.w};
#pragma unroll
        for (int i = 0; i < 4; i++) {
            float2 ai = make_float2(a[i], a[i]);
#pragma unroll
            for (int p = 0; p < 4; p++) ffma2(acc[i][p], ai, wp[p]);
        }
    }

#pragma unroll
    for (int i = 0; i < 4; i++) {
        int g = base + m0 + i;
        if (g >= n) continue;
        float o[8] = {acc[i][0].x, acc[i][0].y, acc[i][1].x, acc[i][1].y,
                      acc[i][2].x, acc[i][2].y, acc[i][3].x, acc[i][3].y};
#pragma unroll
        for (int j = 0; j < 8; j++) {
            o[j] += Bs[j0 + j];
            if (RELU) o[j] = fmaxf(o[j], 0.0f);
        }
        float4 o0 = make_float4(o[0], o[1], o[2], o[3]);
        float4 o1 = make_float4(o[4], o[5], o[6], o[7]);
        if (HOUT) {
            *(float4*)&Hout[g * 64 + j0] = o0;
            *(float4*)&Hout[g * 64 + j0 + 4] = o1;
        }
        if (POOL) {
            int b = batch[g];
            red_add_v4(&g_pooled[b * 64 + j0], o0);
            red_add_v4(&g_pooled[b * 64 + j0 + 4], o1);
        }
    }
}

// ---------------- final: out[g] = (pooled/cnt) . lin_w + lin_b ---------------
__global__ void k_final(const float* __restrict__ lw, const float* __restrict__ lb,
                        float* __restrict__ out, int ng) {
    int g = blockIdx.x * (blockDim.x / 32) + (threadIdx.x >> 5);
    int l = threadIdx.x & 31;
    if (g >= ng) return;
    float v = g_pooled[g * 64 + l] * lw[l] + g_pooled[g * 64 + 32 + l] * lw[32 + l];
#pragma unroll
    for (int o = 16; o > 0; o >>= 1) v += __shfl_down_sync(0xFFFFFFFFu, v, o);
    if (l == 0) out[g] = v / fmaxf(g_cnt[g], 1.0f) + lb[0];
}

// ---------------------------------------------------------------------------
template <class T>
static float* sym_addr(const T& sym) {
    void* p = nullptr;
    cudaGetSymbolAddress(&p, sym);
    return (float*)p;
}

extern "C" void kernel_launch(void* const* d_in, const int* in_sizes, int n_in,
                              void* d_out, int out_size) {
    const float* x   = (const float*)d_in[0];
    const int* ei    = (const int*)d_in[1];
    const int* batch = (const int*)d_in[2];
    const float* W1 = (const float*)d_in[3];
    const float* b1 = (const float*)d_in[4];
    const float* W2 = (const float*)d_in[5];
    const float* b2 = (const float*)d_in[6];
    const float* W3 = (const float*)d_in[7];
    const float* b3 = (const float*)d_in[8];
    const float* lw = (const float*)d_in[9];
    const float* lb = (const float*)d_in[10];
    float* out = (float*)d_out;

    int n  = in_sizes[0] / 11;
    int e  = in_sizes[1] / 2;
    int ng = out_size;
    const int* src = ei;
    const int* dst = ei + e;

    float* p_agg16 = sym_addr(g_agg16);
    float* p_agg   = sym_addr(g_agg);
    float* p_h     = sym_addr(g_h);

    int initN = (NG * 64 > n) ? NG * 64 : n;
    int nb = (n + 1023) / 1024;

    k_init<<<(initN + 255) / 256, 256>>>(n);
    k_deg<<<(e + 255) / 256, 256>>>(dst, e);
    k_scanA<<<nb, 256>>>(n);
    k_scanB<<<1, 256>>>(nb);
    k_scanC<<<nb, 256>>>(n);
    k_fill<<<(e + 255) / 256, 256>>>(src, dst, e);
    k_node<<<(n + 255) / 256, 256>>>(x, batch, n);

    int gb = (n + 63) / 64;

    // layer 1: pull raw 16-padded features, then GEMM (linearity commute)
    k_pull16<<<(n + 63) / 64, 256>>>(n);
    k_gemm<16, 11, 16, true, true, false><<<gb, 128>>>(p_agg16, W1, b1, p_h, nullptr, n);

    // layer 2
    k_pull64<<<(n + 15) / 16, 256>>>(p_h, p_agg, n);
    k_gemm<64, 64, 64, true, true, false><<<gb, 128>>>(p_agg, W2, b2, p_h, nullptr, n);

    // layer 3 (no relu; fused pooling reduce, h3 never materialized)
    k_pull64<<<(n + 15) / 16, 256>>>(p_h, p_agg, n);
    k_gemm<64, 64, 64, false, false, true><<<gb, 128>>>(p_agg, W3, b3, nullptr, batch, n);

    k_final<<<(ng + 7) / 8, 256>>>(lw, lb, out, ng);
}

// round 3
// speedup vs baseline: 1.8416x; 1.3984x over previous
#include <cuda_runtime.h>

#define NN 200000
#define NE 1000000
#define NG 4096

// ------------------------- scratch (static device globals) -----------------
static __device__ int   g_degi[NN];          // zeroed at end of k_scanC (replay-safe)
static __device__ int   g_off[NN + 1];
static __device__ int   g_cursor[NN];
static __device__ int   g_csrc[NE];
static __device__ int   g_bsum[256];
static __device__ float g_dis[NN];
static __device__ float g_x16[NN * 16];      // x * dis, padded to 16
static __device__ float g_h1[NN * 64];       // h1 * dis
static __device__ float g_h2[NN * 64];       // h2 * dis
static __device__ float g_pool1[NG];         // zeroed at end of k_final
static __device__ float g_cnt[NG];           // zeroed at end of k_final
static __device__ float g_w3l[64];           // W3 @ lin_w
static __device__ float g_c0;                // b3.lin_w + lin_b

__device__ __forceinline__ void red_add_f32(float* p, float v) {
    asm volatile("red.global.add.f32 [%0], %1;" :: "l"(p), "f"(v) : "memory");
}

// packed f32x2 FMA (Blackwell): acc = a*b + acc
__device__ __forceinline__ void ffma2(float2& acc, float2 a, float2 b) {
    asm("fma.rn.f32x2 %0, %1, %2, %0;"
        : "+l"(*reinterpret_cast<unsigned long long*>(&acc))
        : "l"(*reinterpret_cast<const unsigned long long*>(&a)),
          "l"(*reinterpret_cast<const unsigned long long*>(&b)));
}

// ------------- prep: w3l = W3 @ lin_w ; c0 = b3.lin_w + lin_b ---------------
__global__ void k_prep(const float* __restrict__ W3, const float* __restrict__ b3,
                       const float* __restrict__ lw, const float* __restrict__ lb) {
    int t = threadIdx.x;  // 64 threads
    float s = 0.0f;
    for (int j = 0; j < 64; j++) s += W3[t * 64 + j] * lw[j];
    g_w3l[t] = s;
    if (t == 0) {
        float c = lb[0];
        for (int j = 0; j < 64; j++) c += b3[j] * lw[j];
        g_c0 = c;
    }
}

// ------------------------- degree histogram ---------------------------------
__global__ void k_deg(const int* __restrict__ dst, int e) {
    int i = blockIdx.x * blockDim.x + threadIdx.x;
    if (i < e) atomicAdd(&g_degi[dst[i]], 1);
}

// -------- scanA: per-1024-chunk degree sums ----------------------------------
__global__ void k_scanA(int n) {
    __shared__ int ws[8];
    int b = blockIdx.x, t = threadIdx.x;
    int base = b * 1024;
    int sum = 0;
    for (int i = t; i < 1024; i += 256) {
        int g = base + i;
        if (g < n) sum += g_degi[g];
    }
#pragma unroll
    for (int o = 16; o; o >>= 1) sum += __shfl_down_sync(~0u, sum, o);
    if ((t & 31) == 0) ws[t >> 5] = sum;
    __syncthreads();
    if (t == 0) {
        int s = 0;
#pragma unroll
        for (int w = 0; w < 8; w++) s += ws[w];
        g_bsum[b] = s;
    }
}

// -------- scanC: offsets + cursor + dis + x~ staging + graph counts ----------
// Also computes its own block offset (sum of g_bsum[0..b)) and zeroes g_degi.
__global__ void k_scanC(const float* __restrict__ x, const int* __restrict__ batch, int n) {
    __shared__ int ws[8];
    __shared__ int s_boff;
    int b = blockIdx.x, t = threadIdx.x;

    // block offset = prefix sum of chunk sums
    {
        int p = (t < b) ? g_bsum[t] : 0;
#pragma unroll
        for (int o = 16; o; o >>= 1) p += __shfl_down_sync(~0u, p, o);
        if ((t & 31) == 0) ws[t >> 5] = p;
        __syncthreads();
        if (t == 0) {
            int s = 0;
#pragma unroll
            for (int w = 0; w < 8; w++) s += ws[w];
            s_boff = s;
        }
        __syncthreads();
    }

    int base = b * 1024 + t * 4;
    int d[4];
#pragma unroll
    for (int i = 0; i < 4; i++) {
        int g = base + i;
        d[i] = (g < n) ? g_degi[g] : 0;
        if (g < n) g_degi[g] = 0;  // reset for next graph replay
    }
    int tot = d[0] + d[1] + d[2] + d[3];
    int inc = tot;
#pragma unroll
    for (int o = 1; o < 32; o <<= 1) {
        int u = __shfl_up_sync(~0u, inc, o);
        if ((t & 31) >= o) inc += u;
    }
    if ((t & 31) == 31) ws[t >> 5] = inc;
    __syncthreads();
    if (t < 8) {
        int w = ws[t];
#pragma unroll
        for (int o = 1; o < 8; o <<= 1) {
            int u = __shfl_up_sync(0xFFu, w, o);
            if (t >= o) w += u;
        }
        ws[t] = w;
    }
    __syncthreads();
    int off = inc - tot + ((t >= 32) ? ws[(t >> 5) - 1] : 0) + s_boff;

#pragma unroll
    for (int i = 0; i < 4; i++) {
        int g = base + i;
        if (g < n) {
            g_off[g] = off;
            g_cursor[g] = off;
            float dis = rsqrtf((float)(d[i] + 1));
            g_dis[g] = dis;
            if (g == n - 1) g_off[n] = off + d[i];
            // stage x~ = x * dis, padded to 16
            float v[16];
#pragma unroll
            for (int c = 0; c < 11; c++) v[c] = x[g * 11 + c] * dis;
#pragma unroll
            for (int c = 11; c < 16; c++) v[c] = 0.0f;
#pragma unroll
            for (int q = 0; q < 4; q++)
                *(float4*)&g_x16[g * 16 + q * 4] =
                    make_float4(v[q * 4], v[q * 4 + 1], v[q * 4 + 2], v[q * 4 + 3]);
            off += d[i];
        }
    }
    // graph node counts (dedup across the 4 consecutive, batch-sorted nodes)
    int cb = -1; float cc = 0.0f;
#pragma unroll
    for (int i = 0; i < 4; i++) {
        int g = base + i;
        if (g >= n) continue;
        int bb = batch[g];
        if (bb == cb) cc += 1.0f;
        else {
            if (cb >= 0) atomicAdd(&g_cnt[cb], cc);
            cb = bb; cc = 1.0f;
        }
    }
    if (cb >= 0) atomicAdd(&g_cnt[cb], cc);
}

// ------------------------- CSR fill -----------------------------------------
__global__ void k_fill(const int* __restrict__ src, const int* __restrict__ dst, int e) {
    int i = blockIdx.x * blockDim.x + threadIdx.x;
    if (i >= e) return;
    int p = atomicAdd(&g_cursor[dst[i]], 1);
    g_csrc[p] = src[i];
}

// ------------- layer 1 fused: pull(16-dim x~) + GEMM K=16 -> h1~ -------------
__global__ void __launch_bounds__(256)
k_layer1(const float* __restrict__ W, const float* __restrict__ bias, int n) {
    __shared__ float Am[16 * 73];
    __shared__ float Ws[16 * 64];
    __shared__ float Bs[64];
    const int t = threadIdx.x;
    const int base = blockIdx.x * 64;

    for (int i = t; i < 16 * 64; i += 256) Ws[i] = (i < 11 * 64) ? W[i] : 0.0f;
    if (t < 64) Bs[t] = bias[t];

    // pull: 4 lanes/node, 64 nodes/block
    {
        int lane = t & 3, slot = t >> 2;
        int node = base + slot;
        float4 acc = make_float4(0.f, 0.f, 0.f, 0.f);
        float dd = 0.0f;
        if (node < n) {
            acc = *(const float4*)&g_x16[node * 16 + lane * 4];
            int s0 = g_off[node], s1 = g_off[node + 1];
            int k = s0;
            for (; k + 1 < s1; k += 2) {
                int a = g_csrc[k], c = g_csrc[k + 1];
                float4 va = *(const float4*)&g_x16[a * 16 + lane * 4];
                float4 vc = *(const float4*)&g_x16[c * 16 + lane * 4];
                acc.x += va.x + vc.x; acc.y += va.y + vc.y;
                acc.z += va.z + vc.z; acc.w += va.w + vc.w;
            }
            if (k < s1) {
                int a = g_csrc[k];
                float4 va = *(const float4*)&g_x16[a * 16 + lane * 4];
                acc.x += va.x; acc.y += va.y; acc.z += va.z; acc.w += va.w;
            }
            dd = g_dis[node];
        }
        Am[(lane * 4 + 0) * 73 + slot] = acc.x * dd;
        Am[(lane * 4 + 1) * 73 + slot] = acc.y * dd;
        Am[(lane * 4 + 2) * 73 + slot] = acc.z * dd;
        Am[(lane * 4 + 3) * 73 + slot] = acc.w * dd;
    }
    __syncthreads();

    // GEMM: 2 nodes x 8 outs per thread
    const int m0 = (t & 31) * 2;
    const int j0 = (t >> 5) * 8;
    float2 acc2[2][4];
#pragma unroll
    for (int i = 0; i < 2; i++)
#pragma unroll
        for (int p = 0; p < 4; p++) acc2[i][p] = make_float2(0.f, 0.f);

#pragma unroll
    for (int k = 0; k < 16; k++) {
        float a0 = Am[k * 73 + m0];
        float a1 = Am[k * 73 + m0 + 1];
        float4 w0 = *(const float4*)&Ws[k * 64 + j0];
        float4 w1 = *(const float4*)&Ws[k * 64 + j0 + 4];
        float2 wp[4] = {{w0.x, w0.y}, {w0.z, w0.w}, {w1.x, w1.y}, {w1.z, w1.w}};
        float2 A0 = make_float2(a0, a0), A1 = make_float2(a1, a1);
#pragma unroll
        for (int p = 0; p < 4; p++) { ffma2(acc2[0][p], A0, wp[p]); ffma2(acc2[1][p], A1, wp[p]); }
    }

#pragma unroll
    for (int i = 0; i < 2; i++) {
        int g = base + m0 + i;
        if (g >= n) continue;
        float dd = g_dis[g];
        float o[8] = {acc2[i][0].x, acc2[i][0].y, acc2[i][1].x, acc2[i][1].y,
                      acc2[i][2].x, acc2[i][2].y, acc2[i][3].x, acc2[i][3].y};
#pragma unroll
        for (int j = 0; j < 8; j++) o[j] = fmaxf(o[j] + Bs[j0 + j], 0.0f) * dd;
        *(float4*)&g_h1[g * 64 + j0]     = make_float4(o[0], o[1], o[2], o[3]);
        *(float4*)&g_h1[g * 64 + j0 + 4] = make_float4(o[4], o[5], o[6], o[7]);
    }
}

// ------------- layer 2 fused: pull(64-dim h1~) + GEMM K=64 -> h2~ ------------
__global__ void __launch_bounds__(256)
k_layer2(const float* __restrict__ W, const float* __restrict__ bias, int n) {
    __shared__ float Am[64 * 73];
    __shared__ float Ws[64 * 64];
    __shared__ float Bs[64];
    const int t = threadIdx.x;
    const int base = blockIdx.x * 64;

    for (int i = t * 4; i < 64 * 64; i += 1024)
        *(float4*)&Ws[i] = *(const float4*)&W[i];
    if (t < 64) Bs[t] = bias[t];

    // pull: 16 lanes/node, 4 serial nodes per thread
    {
        int lane = t & 15, slot = t >> 4;
#pragma unroll
        for (int s = 0; s < 4; s++) {
            int node = base + slot + 16 * s;
            float4 acc = make_float4(0.f, 0.f, 0.f, 0.f);
            float dd = 0.0f;
            if (node < n) {
                acc = *(const float4*)&g_h1[node * 64 + lane * 4];
                int s0 = g_off[node], s1 = g_off[node + 1];
                int k = s0;
                for (; k + 1 < s1; k += 2) {
                    int a = g_csrc[k], c = g_csrc[k + 1];
                    float4 va = *(const float4*)&g_h1[a * 64 + lane * 4];
                    float4 vc = *(const float4*)&g_h1[c * 64 + lane * 4];
                    acc.x += va.x + vc.x; acc.y += va.y + vc.y;
                    acc.z += va.z + vc.z; acc.w += va.w + vc.w;
                }
                if (k < s1) {
                    int a = g_csrc[k];
                    float4 va = *(const float4*)&g_h1[a * 64 + lane * 4];
                    acc.x += va.x; acc.y += va.y; acc.z += va.z; acc.w += va.w;
                }
                dd = g_dis[node];
            }
            int m = slot + 16 * s;
            Am[(lane * 4 + 0) * 73 + m] = acc.x * dd;
            Am[(lane * 4 + 1) * 73 + m] = acc.y * dd;
            Am[(lane * 4 + 2) * 73 + m] = acc.z * dd;
            Am[(lane * 4 + 3) * 73 + m] = acc.w * dd;
        }
    }
    __syncthreads();

    const int m0 = (t & 31) * 2;
    const int j0 = (t >> 5) * 8;
    float2 acc2[2][4];
#pragma unroll
    for (int i = 0; i < 2; i++)
#pragma unroll
        for (int p = 0; p < 4; p++) acc2[i][p] = make_float2(0.f, 0.f);

#pragma unroll 8
    for (int k = 0; k < 64; k++) {
        float a0 = Am[k * 73 + m0];
        float a1 = Am[k * 73 + m0 + 1];
        float4 w0 = *(const float4*)&Ws[k * 64 + j0];
        float4 w1 = *(const float4*)&Ws[k * 64 + j0 + 4];
        float2 wp[4] = {{w0.x, w0.y}, {w0.z, w0.w}, {w1.x, w1.y}, {w1.z, w1.w}};
        float2 A0 = make_float2(a0, a0), A1 = make_float2(a1, a1);
#pragma unroll
        for (int p = 0; p < 4; p++) { ffma2(acc2[0][p], A0, wp[p]); ffma2(acc2[1][p], A1, wp[p]); }
    }

#pragma unroll
    for (int i = 0; i < 2; i++) {
        int g = base + m0 + i;
        if (g >= n) continue;
        float dd = g_dis[g];
        float o[8] = {acc2[i][0].x, acc2[i][0].y, acc2[i][1].x, acc2[i][1].y,
                      acc2[i][2].x, acc2[i][2].y, acc2[i][3].x, acc2[i][3].y};
#pragma unroll
        for (int j = 0; j < 8; j++) o[j] = fmaxf(o[j] + Bs[j0 + j], 0.0f) * dd;
        *(float4*)&g_h2[g * 64 + j0]     = make_float4(o[0], o[1], o[2], o[3]);
        *(float4*)&g_h2[g * 64 + j0 + 4] = make_float4(o[4], o[5], o[6], o[7]);
    }
}

// ------------- layer 3: pull(h2~) . w3l  ->  scalar red into pool ------------
__global__ void __launch_bounds__(256)
k_layer3(const int* __restrict__ batch, int n) {
    const int t = threadIdx.x;
    const int lane = t & 15, slot = t >> 4;
    const int base = blockIdx.x * 64;
    float4 w = *(const float4*)&g_w3l[lane * 4];
#pragma unroll
    for (int s = 0; s < 4; s++) {
        int node = base + slot + 16 * s;
        bool valid = node < n;
        float4 acc = make_float4(0.f, 0.f, 0.f, 0.f);
        if (valid) {
            acc = *(const float4*)&g_h2[node * 64 + lane * 4];
            int s0 = g_off[node], s1 = g_off[node + 1];
            int k = s0;
            for (; k + 1 < s1; k += 2) {
                int a = g_csrc[k], c = g_csrc[k + 1];
                float4 va = *(const float4*)&g_h2[a * 64 + lane * 4];
                float4 vc = *(const float4*)&g_h2[c * 64 + lane * 4];
                acc.x += va.x + vc.x; acc.y += va.y + vc.y;
                acc.z += va.z + vc.z; acc.w += va.w + vc.w;
            }
            if (k < s1) {
                int a = g_csrc[k];
                float4 va = *(const float4*)&g_h2[a * 64 + lane * 4];
                acc.x += va.x; acc.y += va.y; acc.z += va.z; acc.w += va.w;
            }
        }
        float v = acc.x * w.x + acc.y * w.y + acc.z * w.z + acc.w * w.w;
#pragma unroll
        for (int o = 8; o; o >>= 1) v += __shfl_down_sync(~0u, v, o, 16);
        if (lane == 0 && valid)
            red_add_f32(&g_pool1[batch[node]], v * g_dis[node]);
    }
}

// ------------- final: out[g] = pool1/cnt + c0 ; reset state -------------------
__global__ void k_final(float* __restrict__ out, int ng) {
    int i = blockIdx.x * blockDim.x + threadIdx.x;
    if (i < ng) {
        out[i] = g_pool1[i] / fmaxf(g_cnt[i], 1.0f) + g_c0;
        g_pool1[i] = 0.0f;   // reset for next graph replay
        g_cnt[i] = 0.0f;
    }
}

// ---------------------------------------------------------------------------
extern "C" void kernel_launch(void* const* d_in, const int* in_sizes, int n_in,
                              void* d_out, int out_size) {
    const float* x   = (const float*)d_in[0];
    const int* ei    = (const int*)d_in[1];
    const int* batch = (const int*)d_in[2];
    const float* W1 = (const float*)d_in[3];
    const float* b1 = (const float*)d_in[4];
    const float* W2 = (const float*)d_in[5];
    const float* b2 = (const float*)d_in[6];
    const float* W3 = (const float*)d_in[7];
    const float* b3 = (const float*)d_in[8];
    const float* lw = (const float*)d_in[9];
    const float* lb = (const float*)d_in[10];
    float* out = (float*)d_out;

    int n  = in_sizes[0] / 11;
    int e  = in_sizes[1] / 2;
    int ng = out_size;
    const int* src = ei;
    const int* dst = ei + e;

    int nb = (n + 1023) / 1024;
    int gb = (n + 63) / 64;

    k_prep<<<1, 64>>>(W3, b3, lw, lb);
    k_deg<<<(e + 255) / 256, 256>>>(dst, e);
    k_scanA<<<nb, 256>>>(n);
    k_scanC<<<nb, 256>>>(x, batch, n);
    k_fill<<<(e + 255) / 256, 256>>>(src, dst, e);

    k_layer1<<<gb, 256>>>(W1, b1, n);
    k_layer2<<<gb, 256>>>(W2, b2, n);
    k_layer3<<<gb, 256>>>(batch, n);
    k_final<<<(ng + 255) / 256, 256>>>(out, ng);
}

// round 4
// speedup vs baseline: 2.4452x; 1.3278x over previous
#include <cuda_runtime.h>

#define NN 200000
#define NE 1000000
#define NG 4096

// ------------------------- scratch (static device globals) -----------------
static __device__ int   g_degi[NN];          // zeroed inside k_scanC (replay-safe)
static __device__ int   g_off[NN + 1];
static __device__ int   g_cursor[NN];
static __device__ int   g_csrc[NE];
static __device__ int   g_bsum[256];
static __device__ float g_dis[NN];
static __device__ float g_x16[NN * 16];      // x * dis, padded to 16
static __device__ float g_h1[NN * 64];       // h1 * dis
static __device__ float g_p2[NN];            // (h2 * dis) . w3l  (scalar per node)
static __device__ float g_pool1[NG];         // zeroed at end of k_final
static __device__ float g_cnt[NG];           // zeroed at end of k_final
static __device__ float g_w3l[64];           // W3 @ lin_w
static __device__ float g_c0;                // b3.lin_w + lin_b

__device__ __forceinline__ void red_add_f32(float* p, float v) {
    asm volatile("red.global.add.f32 [%0], %1;" :: "l"(p), "f"(v) : "memory");
}

// packed f32x2 FMA (Blackwell): acc = a*b + acc
__device__ __forceinline__ void ffma2(float2& acc, float2 a, float2 b) {
    asm("fma.rn.f32x2 %0, %1, %2, %0;"
        : "+l"(*reinterpret_cast<unsigned long long*>(&acc))
        : "l"(*reinterpret_cast<const unsigned long long*>(&a)),
          "l"(*reinterpret_cast<const unsigned long long*>(&b)));
}

// --------- degree histogram + (block 0) prep of w3l / c0 --------------------
__global__ void k_deg(const int* __restrict__ dst, int e,
                      const float* __restrict__ W3, const float* __restrict__ b3,
                      const float* __restrict__ lw, const float* __restrict__ lb) {
    if (blockIdx.x == 0 && threadIdx.x < 64) {
        int t = threadIdx.x;
        float s = 0.0f;
        for (int j = 0; j < 64; j++) s += W3[t * 64 + j] * lw[j];
        g_w3l[t] = s;
        if (t == 0) {
            float c = lb[0];
            for (int j = 0; j < 64; j++) c += b3[j] * lw[j];
            g_c0 = c;
        }
    }
    int i = blockIdx.x * blockDim.x + threadIdx.x;
    if (i < e) atomicAdd(&g_degi[dst[i]], 1);
}

// -------- scanA: per-1024-chunk degree sums ----------------------------------
__global__ void k_scanA(int n) {
    __shared__ int ws[8];
    int b = blockIdx.x, t = threadIdx.x;
    int base = b * 1024;
    int sum = 0;
    for (int i = t; i < 1024; i += 256) {
        int g = base + i;
        if (g < n) sum += g_degi[g];
    }
#pragma unroll
    for (int o = 16; o; o >>= 1) sum += __shfl_down_sync(~0u, sum, o);
    if ((t & 31) == 0) ws[t >> 5] = sum;
    __syncthreads();
    if (t == 0) {
        int s = 0;
#pragma unroll
        for (int w = 0; w < 8; w++) s += ws[w];
        g_bsum[b] = s;
    }
}

// -------- scanC: offsets + cursor + dis + graph counts (no staging) ----------
__global__ void k_scanC(const int* __restrict__ batch, int n) {
    __shared__ int ws[8];
    __shared__ int s_boff;
    int b = blockIdx.x, t = threadIdx.x;

    {   // block offset = prefix of chunk sums
        int p = (t < b) ? g_bsum[t] : 0;
#pragma unroll
        for (int o = 16; o; o >>= 1) p += __shfl_down_sync(~0u, p, o);
        if ((t & 31) == 0) ws[t >> 5] = p;
        __syncthreads();
        if (t == 0) {
            int s = 0;
#pragma unroll
            for (int w = 0; w < 8; w++) s += ws[w];
            s_boff = s;
        }
        __syncthreads();
    }

    int base = b * 1024 + t * 4;
    int d[4];
#pragma unroll
    for (int i = 0; i < 4; i++) {
        int g = base + i;
        d[i] = (g < n) ? g_degi[g] : 0;
        if (g < n) g_degi[g] = 0;  // reset for next replay
    }
    int tot = d[0] + d[1] + d[2] + d[3];
    int inc = tot;
#pragma unroll
    for (int o = 1; o < 32; o <<= 1) {
        int u = __shfl_up_sync(~0u, inc, o);
        if ((t & 31) >= o) inc += u;
    }
    if ((t & 31) == 31) ws[t >> 5] = inc;
    __syncthreads();
    if (t < 8) {
        int w = ws[t];
#pragma unroll
        for (int o = 1; o < 8; o <<= 1) {
            int u = __shfl_up_sync(0xFFu, w, o);
            if (t >= o) w += u;
        }
        ws[t] = w;
    }
    __syncthreads();
    int off = inc - tot + ((t >= 32) ? ws[(t >> 5) - 1] : 0) + s_boff;

#pragma unroll
    for (int i = 0; i < 4; i++) {
        int g = base + i;
        if (g < n) {
            g_off[g] = off;
            g_cursor[g] = off;
            g_dis[g] = rsqrtf((float)(d[i] + 1));
            if (g == n - 1) g_off[n] = off + d[i];
            off += d[i];
        }
    }
    // graph node counts (dedup across 4 consecutive batch-sorted nodes)
    int cb = -1; float cc = 0.0f;
#pragma unroll
    for (int i = 0; i < 4; i++) {
        int g = base + i;
        if (g >= n) continue;
        int bb = batch[g];
        if (bb == cb) cc += 1.0f;
        else {
            if (cb >= 0) atomicAdd(&g_cnt[cb], cc);
            cb = bb; cc = 1.0f;
        }
    }
    if (cb >= 0) atomicAdd(&g_cnt[cb], cc);
}

// --------- fused: x staging (coalesced, smem transpose) + CSR fill -----------
// blocks [0, sb): stage 128 nodes each; blocks [sb, sb+fb): CSR fill.
__global__ void __launch_bounds__(256)
k_stage_fill(const float* __restrict__ x, const int* __restrict__ src,
             const int* __restrict__ dst, int n, int e, int sb) {
    int t = threadIdx.x;
    if ((int)blockIdx.x < sb) {
        __shared__ float xs[128 * 11];
        int nbase = blockIdx.x * 128;
        int lim = min(128, n - nbase) * 11;
        for (int i = t; i < lim; i += 256) xs[i] = x[nbase * 11 + i];
        __syncthreads();
        // write 128 nodes * 4 float4 = 512 float4 stores, dis-scaled, padded
        for (int idx = t; idx < 512; idx += 256) {
            int m = idx >> 2, q = idx & 3;
            int g = nbase + m;
            if (g >= n) break;
            float dis = g_dis[g];
            float4 v;
            int c = q * 4;
            v.x = (c + 0 < 11) ? xs[m * 11 + c + 0] * dis : 0.0f;
            v.y = (c + 1 < 11) ? xs[m * 11 + c + 1] * dis : 0.0f;
            v.z = (c + 2 < 11) ? xs[m * 11 + c + 2] * dis : 0.0f;
            v.w = (c + 3 < 11) ? xs[m * 11 + c + 3] * dis : 0.0f;
            *(float4*)&g_x16[g * 16 + c] = v;
        }
    } else {
        int i = (blockIdx.x - sb) * 256 + t;
        if (i < e) {
            int p = atomicAdd(&g_cursor[dst[i]], 1);
            g_csrc[p] = src[i];
        }
    }
}

// ------------- layer 1 fused: pull(16-dim x~) + GEMM K=16 -> h1~ -------------
__global__ void __launch_bounds__(256)
k_layer1(const float* __restrict__ W, const float* __restrict__ bias, int n) {
    __shared__ float Am[16 * 73];
    __shared__ float Ws[16 * 64];
    __shared__ float Bs[64];
    const int t = threadIdx.x;
    const int base = blockIdx.x * 64;

    for (int i = t; i < 16 * 64; i += 256) Ws[i] = (i < 11 * 64) ? W[i] : 0.0f;
    if (t < 64) Bs[t] = bias[t];

    {   // pull: 4 lanes/node, 64 nodes/block
        int lane = t & 3, slot = t >> 2;
        int node = base + slot;
        float4 acc = make_float4(0.f, 0.f, 0.f, 0.f);
        float dd = 0.0f;
        if (node < n) {
            acc = *(const float4*)&g_x16[node * 16 + lane * 4];
            int s0 = g_off[node], s1 = g_off[node + 1];
            int k = s0;
            for (; k + 3 < s1; k += 4) {
                int a = g_csrc[k], b2i = g_csrc[k + 1], c = g_csrc[k + 2], d = g_csrc[k + 3];
                float4 va = *(const float4*)&g_x16[a * 16 + lane * 4];
                float4 vb = *(const float4*)&g_x16[b2i * 16 + lane * 4];
                float4 vc = *(const float4*)&g_x16[c * 16 + lane * 4];
                float4 vd = *(const float4*)&g_x16[d * 16 + lane * 4];
                acc.x += (va.x + vb.x) + (vc.x + vd.x);
                acc.y += (va.y + vb.y) + (vc.y + vd.y);
                acc.z += (va.z + vb.z) + (vc.z + vd.z);
                acc.w += (va.w + vb.w) + (vc.w + vd.w);
            }
            for (; k < s1; k++) {
                int a = g_csrc[k];
                float4 va = *(const float4*)&g_x16[a * 16 + lane * 4];
                acc.x += va.x; acc.y += va.y; acc.z += va.z; acc.w += va.w;
            }
            dd = g_dis[node];
        }
        Am[(lane * 4 + 0) * 73 + slot] = acc.x * dd;
        Am[(lane * 4 + 1) * 73 + slot] = acc.y * dd;
        Am[(lane * 4 + 2) * 73 + slot] = acc.z * dd;
        Am[(lane * 4 + 3) * 73 + slot] = acc.w * dd;
    }
    __syncthreads();

    const int m0 = (t & 31) * 2;
    const int j0 = (t >> 5) * 8;
    float2 acc2[2][4];
#pragma unroll
    for (int i = 0; i < 2; i++)
#pragma unroll
        for (int p = 0; p < 4; p++) acc2[i][p] = make_float2(0.f, 0.f);

#pragma unroll
    for (int k = 0; k < 16; k++) {
        float a0 = Am[k * 73 + m0];
        float a1 = Am[k * 73 + m0 + 1];
        float4 w0 = *(const float4*)&Ws[k * 64 + j0];
        float4 w1 = *(const float4*)&Ws[k * 64 + j0 + 4];
        float2 wp[4] = {{w0.x, w0.y}, {w0.z, w0.w}, {w1.x, w1.y}, {w1.z, w1.w}};
        float2 A0 = make_float2(a0, a0), A1 = make_float2(a1, a1);
#pragma unroll
        for (int p = 0; p < 4; p++) { ffma2(acc2[0][p], A0, wp[p]); ffma2(acc2[1][p], A1, wp[p]); }
    }

#pragma unroll
    for (int i = 0; i < 2; i++) {
        int g = base + m0 + i;
        if (g >= n) continue;
        float dd = g_dis[g];
        float o[8] = {acc2[i][0].x, acc2[i][0].y, acc2[i][1].x, acc2[i][1].y,
                      acc2[i][2].x, acc2[i][2].y, acc2[i][3].x, acc2[i][3].y};
#pragma unroll
        for (int j = 0; j < 8; j++) o[j] = fmaxf(o[j] + Bs[j0 + j], 0.0f) * dd;
        *(float4*)&g_h1[g * 64 + j0]     = make_float4(o[0], o[1], o[2], o[3]);
        *(float4*)&g_h1[g * 64 + j0 + 4] = make_float4(o[4], o[5], o[6], o[7]);
    }
}

// -- layer 2 fused: pull(64-dim h1~) + GEMM K=64 -> p2 scalar (no h2 write) ---
__global__ void __launch_bounds__(256)
k_layer2(const float* __restrict__ W, const float* __restrict__ bias, int n) {
    __shared__ float Am[64 * 73];
    __shared__ float Ws[64 * 64];
    __shared__ float Bs[64];
    __shared__ float W3s[64];
    __shared__ float Ps[64];
    const int t = threadIdx.x;
    const int base = blockIdx.x * 64;

    for (int i = t * 4; i < 64 * 64; i += 1024)
        *(float4*)&Ws[i] = *(const float4*)&W[i];
    if (t < 64) { Bs[t] = bias[t]; W3s[t] = g_w3l[t]; Ps[t] = 0.0f; }

    {   // pull: 16 lanes/node, 4 serial nodes per thread
        int lane = t & 15, slot = t >> 4;
#pragma unroll
        for (int s = 0; s < 4; s++) {
            int node = base + slot + 16 * s;
            float4 acc = make_float4(0.f, 0.f, 0.f, 0.f);
            float dd = 0.0f;
            if (node < n) {
                acc = *(const float4*)&g_h1[node * 64 + lane * 4];
                int s0 = g_off[node], s1 = g_off[node + 1];
                int k = s0;
                for (; k + 3 < s1; k += 4) {
                    int a = g_csrc[k], b2i = g_csrc[k + 1], c = g_csrc[k + 2], d = g_csrc[k + 3];
                    float4 va = *(const float4*)&g_h1[a * 64 + lane * 4];
                    float4 vb = *(const float4*)&g_h1[b2i * 64 + lane * 4];
                    float4 vc = *(const float4*)&g_h1[c * 64 + lane * 4];
                    float4 vd = *(const float4*)&g_h1[d * 64 + lane * 4];
                    acc.x += (va.x + vb.x) + (vc.x + vd.x);
                    acc.y += (va.y + vb.y) + (vc.y + vd.y);
                    acc.z += (va.z + vb.z) + (vc.z + vd.z);
                    acc.w += (va.w + vb.w) + (vc.w + vd.w);
                }
                for (; k < s1; k++) {
                    int a = g_csrc[k];
                    float4 va = *(const float4*)&g_h1[a * 64 + lane * 4];
                    acc.x += va.x; acc.y += va.y; acc.z += va.z; acc.w += va.w;
                }
                dd = g_dis[node];
            }
            int m = slot + 16 * s;
            Am[(lane * 4 + 0) * 73 + m] = acc.x * dd;
            Am[(lane * 4 + 1) * 73 + m] = acc.y * dd;
            Am[(lane * 4 + 2) * 73 + m] = acc.z * dd;
            Am[(lane * 4 + 3) * 73 + m] = acc.w * dd;
        }
    }
    __syncthreads();

    const int m0 = (t & 31) * 2;
    const int j0 = (t >> 5) * 8;
    float2 acc2[2][4];
#pragma unroll
    for (int i = 0; i < 2; i++)
#pragma unroll
        for (int p = 0; p < 4; p++) acc2[i][p] = make_float2(0.f, 0.f);

#pragma unroll 8
    for (int k = 0; k < 64; k++) {
        float a0 = Am[k * 73 + m0];
        float a1 = Am[k * 73 + m0 + 1];
        float4 w0 = *(const float4*)&Ws[k * 64 + j0];
        float4 w1 = *(const float4*)&Ws[k * 64 + j0 + 4];
        float2 wp[4] = {{w0.x, w0.y}, {w0.z, w0.w}, {w1.x, w1.y}, {w1.z, w1.w}};
        float2 A0 = make_float2(a0, a0), A1 = make_float2(a1, a1);
#pragma unroll
        for (int p = 0; p < 4; p++) { ffma2(acc2[0][p], A0, wp[p]); ffma2(acc2[1][p], A1, wp[p]); }
    }

    float4 w3a = *(const float4*)&W3s[j0];
    float4 w3b = *(const float4*)&W3s[j0 + 4];
#pragma unroll
    for (int i = 0; i < 2; i++) {
        int g = base + m0 + i;
        if (g >= n) continue;
        float dd = g_dis[g];
        float o[8] = {acc2[i][0].x, acc2[i][0].y, acc2[i][1].x, acc2[i][1].y,
                      acc2[i][2].x, acc2[i][2].y, acc2[i][3].x, acc2[i][3].y};
#pragma unroll
        for (int j = 0; j < 8; j++) o[j] = fmaxf(o[j] + Bs[j0 + j], 0.0f) * dd;
        // partial dot with w3l -> per-node scalar p2 (smem reduce over 8 j-threads)
        float part = o[0] * w3a.x + o[1] * w3a.y + o[2] * w3a.z + o[3] * w3a.w +
                     o[4] * w3b.x + o[5] * w3b.y + o[6] * w3b.z + o[7] * w3b.w;
        atomicAdd(&Ps[m0 + i], part);
    }
    __syncthreads();
    if (t < 64 && base + t < n) g_p2[base + t] = Ps[t];
}

// ------ layer 3: per-node scalar pull of p2 -> red into graph pool ----------
__global__ void __launch_bounds__(256)
k_layer3(const int* __restrict__ batch, int n) {
    int i = blockIdx.x * 256 + threadIdx.x;
    if (i >= n) return;
    float s = g_p2[i];
    int s0 = g_off[i], s1 = g_off[i + 1];
    int k = s0;
    for (; k + 3 < s1; k += 4) {
        float a = g_p2[g_csrc[k]];
        float b = g_p2[g_csrc[k + 1]];
        float c = g_p2[g_csrc[k + 2]];
        float d = g_p2[g_csrc[k + 3]];
        s += (a + b) + (c + d);
    }
    for (; k < s1; k++) s += g_p2[g_csrc[k]];
    red_add_f32(&g_pool1[batch[i]], s * g_dis[i]);
}

// ------------- final: out[g] = pool1/cnt + c0 ; reset state ------------------
__global__ void k_final(float* __restrict__ out, int ng) {
    int i = blockIdx.x * blockDim.x + threadIdx.x;
    if (i < ng) {
        out[i] = g_pool1[i] / fmaxf(g_cnt[i], 1.0f) + g_c0;
        g_pool1[i] = 0.0f;   // reset for next replay
        g_cnt[i] = 0.0f;
    }
}

// ---------------------------------------------------------------------------
extern "C" void kernel_launch(void* const* d_in, const int* in_sizes, int n_in,
                              void* d_out, int out_size) {
    const float* x   = (const float*)d_in[0];
    const int* ei    = (const int*)d_in[1];
    const int* batch = (const int*)d_in[2];
    const float* W1 = (const float*)d_in[3];
    const float* b1 = (const float*)d_in[4];
    const float* W2 = (const float*)d_in[5];
    const float* b2 = (const float*)d_in[6];
    const float* W3 = (const float*)d_in[7];
    const float* b3 = (const float*)d_in[8];
    const float* lw = (const float*)d_in[9];
    const float* lb = (const float*)d_in[10];
    float* out = (float*)d_out;

    int n  = in_sizes[0] / 11;
    int e  = in_sizes[1] / 2;
    int ng = out_size;
    const int* src = ei;
    const int* dst = ei + e;

    int nb = (n + 1023) / 1024;
    int gb = (n + 63) / 64;
    int sb = (n + 127) / 128;           // staging blocks
    int fb = (e + 255) / 256;           // fill blocks

    k_deg<<<fb, 256>>>(dst, e, W3, b3, lw, lb);
    k_scanA<<<nb, 256>>>(n);
    k_scanC<<<nb, 256>>>(batch, n);
    k_stage_fill<<<sb + fb, 256>>>(x, src, dst, n, e, sb);

    k_layer1<<<gb, 256>>>(W1, b1, n);
    k_layer2<<<gb, 256>>>(W2, b2, n);
    k_layer3<<<(n + 255) / 256, 256>>>(batch, n);
    k_final<<<(ng + 255) / 256, 256>>>(out, ng);
}

// round 5
// speedup vs baseline: 2.7789x; 1.1365x over previous
#include <cuda_runtime.h>
#include <cuda_fp16.h>

#define NN 200000
#define NE 1000000
#define NG 4096

// ------------------------- scratch (static device globals) -----------------
static __device__ int    g_degi[NN];          // zeroed inside k_scanC (replay-safe)
static __device__ int    g_off[NN + 1];
static __device__ int    g_cursor[NN];
static __device__ int    g_csrc[NE];
static __device__ int    g_bsum[256];
static __device__ float  g_dis[NN];
static __device__ float  g_x16[NN * 16];      // x * dis, padded to 16 (fp32)
static __device__ __half g_h1h[NN * 64];      // h1 * dis (fp16)
static __device__ float  g_p2[NN];            // (h2 * dis) . w3l  (scalar per node)
static __device__ float  g_pool1[NG];         // zeroed at end of k_final
static __device__ float  g_cnt[NG];           // zeroed at end of k_final
static __device__ float  g_w3l[64];           // W3 @ lin_w
static __device__ float  g_c0;                // b3.lin_w + lin_b

__device__ __forceinline__ void red_add_f32(float* p, float v) {
    asm volatile("red.global.add.f32 [%0], %1;" :: "l"(p), "f"(v) : "memory");
}

// packed f32x2 FMA (Blackwell): acc = a*b + acc
__device__ __forceinline__ void ffma2(float2& acc, float2 a, float2 b) {
    asm("fma.rn.f32x2 %0, %1, %2, %0;"
        : "+l"(*reinterpret_cast<unsigned long long*>(&acc))
        : "l"(*reinterpret_cast<const unsigned long long*>(&a)),
          "l"(*reinterpret_cast<const unsigned long long*>(&b)));
}

// --------- degree histogram (4 edges/thread) + (block 0) prep w3l/c0 --------
__global__ void k_deg(const int* __restrict__ dst, int e,
                      const float* __restrict__ W3, const float* __restrict__ b3,
                      const float* __restrict__ lw, const float* __restrict__ lb) {
    if (blockIdx.x == 0 && threadIdx.x < 64) {
        int t = threadIdx.x;
        float s = 0.0f;
        for (int j = 0; j < 64; j++) s += W3[t * 64 + j] * lw[j];
        g_w3l[t] = s;
        if (t == 0) {
            float c = lb[0];
            for (int j = 0; j < 64; j++) c += b3[j] * lw[j];
            g_c0 = c;
        }
    }
    int i = (blockIdx.x * 256 + threadIdx.x) * 4;
    if (i + 3 < e) {
        int4 d4 = *(const int4*)&dst[i];
        atomicAdd(&g_degi[d4.x], 1);
        atomicAdd(&g_degi[d4.y], 1);
        atomicAdd(&g_degi[d4.z], 1);
        atomicAdd(&g_degi[d4.w], 1);
    } else {
        for (; i < e; i++) atomicAdd(&g_degi[dst[i]], 1);
    }
}

// -------- scanA: per-1024-chunk degree sums ----------------------------------
__global__ void k_scanA(int n) {
    __shared__ int ws[8];
    int b = blockIdx.x, t = threadIdx.x;
    int base = b * 1024;
    int sum = 0;
    for (int i = t; i < 1024; i += 256) {
        int g = base + i;
        if (g < n) sum += g_degi[g];
    }
#pragma unroll
    for (int o = 16; o; o >>= 1) sum += __shfl_down_sync(~0u, sum, o);
    if ((t & 31) == 0) ws[t >> 5] = sum;
    __syncthreads();
    if (t == 0) {
        int s = 0;
#pragma unroll
        for (int w = 0; w < 8; w++) s += ws[w];
        g_bsum[b] = s;
    }
}

// -------- scanC: offsets + cursor + dis + graph counts ------------------------
__global__ void k_scanC(const int* __restrict__ batch, int n) {
    __shared__ int ws[8];
    __shared__ int s_boff;
    int b = blockIdx.x, t = threadIdx.x;

    {   // block offset = prefix of chunk sums
        int p = (t < b) ? g_bsum[t] : 0;
#pragma unroll
        for (int o = 16; o; o >>= 1) p += __shfl_down_sync(~0u, p, o);
        if ((t & 31) == 0) ws[t >> 5] = p;
        __syncthreads();
        if (t == 0) {
            int s = 0;
#pragma unroll
            for (int w = 0; w < 8; w++) s += ws[w];
            s_boff = s;
        }
        __syncthreads();
    }

    int base = b * 1024 + t * 4;
    int d[4];
#pragma unroll
    for (int i = 0; i < 4; i++) {
        int g = base + i;
        d[i] = (g < n) ? g_degi[g] : 0;
        if (g < n) g_degi[g] = 0;  // reset for next replay
    }
    int tot = d[0] + d[1] + d[2] + d[3];
    int inc = tot;
#pragma unroll
    for (int o = 1; o < 32; o <<= 1) {
        int u = __shfl_up_sync(~0u, inc, o);
        if ((t & 31) >= o) inc += u;
    }
    if ((t & 31) == 31) ws[t >> 5] = inc;
    __syncthreads();
    if (t < 8) {
        int w = ws[t];
#pragma unroll
        for (int o = 1; o < 8; o <<= 1) {
            int u = __shfl_up_sync(0xFFu, w, o);
            if (t >= o) w += u;
        }
        ws[t] = w;
    }
    __syncthreads();
    int off = inc - tot + ((t >= 32) ? ws[(t >> 5) - 1] : 0) + s_boff;

#pragma unroll
    for (int i = 0; i < 4; i++) {
        int g = base + i;
        if (g < n) {
            g_off[g] = off;
            g_cursor[g] = off;
            g_dis[g] = rsqrtf((float)(d[i] + 1));
            if (g == n - 1) g_off[n] = off + d[i];
            off += d[i];
        }
    }
    // graph node counts (dedup across 4 consecutive batch-sorted nodes)
    int cb = -1; float cc = 0.0f;
#pragma unroll
    for (int i = 0; i < 4; i++) {
        int g = base + i;
        if (g >= n) continue;
        int bb = batch[g];
        if (bb == cb) cc += 1.0f;
        else {
            if (cb >= 0) atomicAdd(&g_cnt[cb], cc);
            cb = bb; cc = 1.0f;
        }
    }
    if (cb >= 0) atomicAdd(&g_cnt[cb], cc);
}

// --------- fused: x staging (coalesced) + CSR fill (4 edges/thread) ----------
__global__ void __launch_bounds__(256)
k_stage_fill(const float* __restrict__ x, const int* __restrict__ src,
             const int* __restrict__ dst, int n, int e, int sb) {
    int t = threadIdx.x;
    if ((int)blockIdx.x < sb) {
        __shared__ float xs[128 * 11];
        int nbase = blockIdx.x * 128;
        int lim = min(128, n - nbase) * 11;
        for (int i = t; i < lim; i += 256) xs[i] = x[nbase * 11 + i];
        __syncthreads();
        for (int idx = t; idx < 512; idx += 256) {
            int m = idx >> 2, q = idx & 3;
            int g = nbase + m;
            if (g >= n) break;
            float dis = g_dis[g];
            float4 v;
            int c = q * 4;
            v.x = (c + 0 < 11) ? xs[m * 11 + c + 0] * dis : 0.0f;
            v.y = (c + 1 < 11) ? xs[m * 11 + c + 1] * dis : 0.0f;
            v.z = (c + 2 < 11) ? xs[m * 11 + c + 2] * dis : 0.0f;
            v.w = (c + 3 < 11) ? xs[m * 11 + c + 3] * dis : 0.0f;
            *(float4*)&g_x16[g * 16 + c] = v;
        }
    } else {
        int i = ((blockIdx.x - sb) * 256 + t) * 4;
        if (i + 3 < e) {
            int4 s4 = *(const int4*)&src[i];
            int4 d4 = *(const int4*)&dst[i];
            g_csrc[atomicAdd(&g_cursor[d4.x], 1)] = s4.x;
            g_csrc[atomicAdd(&g_cursor[d4.y], 1)] = s4.y;
            g_csrc[atomicAdd(&g_cursor[d4.z], 1)] = s4.z;
            g_csrc[atomicAdd(&g_cursor[d4.w], 1)] = s4.w;
        } else {
            for (; i < e; i++)
                g_csrc[atomicAdd(&g_cursor[dst[i]], 1)] = src[i];
        }
    }
}

// ------------- layer 1 fused: pull(16-dim x~) + GEMM K=16 -> h1~ (fp16) ------
__global__ void __launch_bounds__(256)
k_layer1(const float* __restrict__ W, const float* __restrict__ bias, int n) {
    __shared__ float Am[16 * 73];
    __shared__ float Ws[16 * 64];
    __shared__ float Bs[64];
    const int t = threadIdx.x;
    const int base = blockIdx.x * 64;

    for (int i = t; i < 16 * 64; i += 256) Ws[i] = (i < 11 * 64) ? W[i] : 0.0f;
    if (t < 64) Bs[t] = bias[t];

    {   // pull: 4 lanes/node, 64 nodes/block
        int lane = t & 3, slot = t >> 2;
        int node = base + slot;
        float4 acc = make_float4(0.f, 0.f, 0.f, 0.f);
        float dd = 0.0f;
        if (node < n) {
            acc = *(const float4*)&g_x16[node * 16 + lane * 4];
            int s0 = g_off[node], s1 = g_off[node + 1];
            int k = s0;
            for (; k + 3 < s1; k += 4) {
                int a = g_csrc[k], b2i = g_csrc[k + 1], c = g_csrc[k + 2], d = g_csrc[k + 3];
                float4 va = *(const float4*)&g_x16[a * 16 + lane * 4];
                float4 vb = *(const float4*)&g_x16[b2i * 16 + lane * 4];
                float4 vc = *(const float4*)&g_x16[c * 16 + lane * 4];
                float4 vd = *(const float4*)&g_x16[d * 16 + lane * 4];
                acc.x += (va.x + vb.x) + (vc.x + vd.x);
                acc.y += (va.y + vb.y) + (vc.y + vd.y);
                acc.z += (va.z + vb.z) + (vc.z + vd.z);
                acc.w += (va.w + vb.w) + (vc.w + vd.w);
            }
            for (; k < s1; k++) {
                int a = g_csrc[k];
                float4 va = *(const float4*)&g_x16[a * 16 + lane * 4];
                acc.x += va.x; acc.y += va.y; acc.z += va.z; acc.w += va.w;
            }
            dd = g_dis[node];
        }
        Am[(lane * 4 + 0) * 73 + slot] = acc.x * dd;
        Am[(lane * 4 + 1) * 73 + slot] = acc.y * dd;
        Am[(lane * 4 + 2) * 73 + slot] = acc.z * dd;
        Am[(lane * 4 + 3) * 73 + slot] = acc.w * dd;
    }
    __syncthreads();

    const int m0 = (t & 31) * 2;
    const int j0 = (t >> 5) * 8;
    float2 acc2[2][4];
#pragma unroll
    for (int i = 0; i < 2; i++)
#pragma unroll
        for (int p = 0; p < 4; p++) acc2[i][p] = make_float2(0.f, 0.f);

#pragma unroll
    for (int k = 0; k < 16; k++) {
        float a0 = Am[k * 73 + m0];
        float a1 = Am[k * 73 + m0 + 1];
        float4 w0 = *(const float4*)&Ws[k * 64 + j0];
        float4 w1 = *(const float4*)&Ws[k * 64 + j0 + 4];
        float2 wp[4] = {{w0.x, w0.y}, {w0.z, w0.w}, {w1.x, w1.y}, {w1.z, w1.w}};
        float2 A0 = make_float2(a0, a0), A1 = make_float2(a1, a1);
#pragma unroll
        for (int p = 0; p < 4; p++) { ffma2(acc2[0][p], A0, wp[p]); ffma2(acc2[1][p], A1, wp[p]); }
    }

#pragma unroll
    for (int i = 0; i < 2; i++) {
        int g = base + m0 + i;
        if (g >= n) continue;
        float dd = g_dis[g];
        float o[8] = {acc2[i][0].x, acc2[i][0].y, acc2[i][1].x, acc2[i][1].y,
                      acc2[i][2].x, acc2[i][2].y, acc2[i][3].x, acc2[i][3].y};
#pragma unroll
        for (int j = 0; j < 8; j++) o[j] = fmaxf(o[j] + Bs[j0 + j], 0.0f) * dd;
        __half2 h[4];
#pragma unroll
        for (int q = 0; q < 4; q++) h[q] = __floats2half2_rn(o[q * 2], o[q * 2 + 1]);
        *(uint4*)&g_h1h[g * 64 + j0] = *(uint4*)h;
    }
}

// -- layer 2 fused: pull(fp16 h1~) + GEMM K=64 -> p2 scalar; 128-node tile ----
__global__ void __launch_bounds__(256)
k_layer2(const float* __restrict__ W, const float* __restrict__ bias, int n) {
    __shared__ float Am[64 * 136];
    __shared__ float Ws[64 * 64];
    __shared__ float Bs[64];
    __shared__ float W3s[64];
    __shared__ float Ps[128];
    const int t = threadIdx.x;
    const int base = blockIdx.x * 128;

    for (int i = t * 4; i < 64 * 64; i += 1024)
        *(float4*)&Ws[i] = *(const float4*)&W[i];
    if (t < 64) { Bs[t] = bias[t]; W3s[t] = g_w3l[t]; }
    if (t < 128) Ps[t] = 0.0f;

    {   // pull: 8 lanes/node (fp16 rows, 16B each), 4 serial nodes per thread
        int lane = t & 7, slot = t >> 3;   // 32 slots
#pragma unroll
        for (int s = 0; s < 4; s++) {
            int node = base + slot + 32 * s;
            float acc[8] = {0, 0, 0, 0, 0, 0, 0, 0};
            float dd = 0.0f;
            if (node < n) {
                uint4 r = *(const uint4*)&g_h1h[node * 64 + lane * 8];
                __half2* hp = (__half2*)&r;
#pragma unroll
                for (int q = 0; q < 4; q++) {
                    float2 f = __half22float2(hp[q]);
                    acc[q * 2] = f.x; acc[q * 2 + 1] = f.y;
                }
                int s0 = g_off[node], s1 = g_off[node + 1];
                int k = s0;
                for (; k + 1 < s1; k += 2) {
                    int a = g_csrc[k], b2i = g_csrc[k + 1];
                    uint4 ra = *(const uint4*)&g_h1h[a * 64 + lane * 8];
                    uint4 rb = *(const uint4*)&g_h1h[b2i * 64 + lane * 8];
                    __half2* pa = (__half2*)&ra;
                    __half2* pb = (__half2*)&rb;
#pragma unroll
                    for (int q = 0; q < 4; q++) {
                        float2 fa = __half22float2(pa[q]);
                        float2 fb = __half22float2(pb[q]);
                        acc[q * 2]     += fa.x + fb.x;
                        acc[q * 2 + 1] += fa.y + fb.y;
                    }
                }
                if (k < s1) {
                    int a = g_csrc[k];
                    uint4 ra = *(const uint4*)&g_h1h[a * 64 + lane * 8];
                    __half2* pa = (__half2*)&ra;
#pragma unroll
                    for (int q = 0; q < 4; q++) {
                        float2 fa = __half22float2(pa[q]);
                        acc[q * 2] += fa.x; acc[q * 2 + 1] += fa.y;
                    }
                }
                dd = g_dis[node];
            }
            int m = slot + 32 * s;
#pragma unroll
            for (int q = 0; q < 8; q++)
                Am[(lane * 8 + q) * 136 + m] = acc[q] * dd;
        }
    }
    __syncthreads();

    // GEMM: 4 nodes x 8 outs per thread; per-warp uniform j0 (broadcast W reads)
    const int m0 = (t & 31) * 4;
    const int j0 = (t >> 5) * 8;
    float2 acc2[4][4];
#pragma unroll
    for (int i = 0; i < 4; i++)
#pragma unroll
        for (int p = 0; p < 4; p++) acc2[i][p] = make_float2(0.f, 0.f);

#pragma unroll 8
    for (int k = 0; k < 64; k++) {
        float4 a4 = *(const float4*)&Am[k * 136 + m0];
        float4 w0 = *(const float4*)&Ws[k * 64 + j0];
        float4 w1 = *(const float4*)&Ws[k * 64 + j0 + 4];
        float2 wp[4] = {{w0.x, w0.y}, {w0.z, w0.w}, {w1.x, w1.y}, {w1.z, w1.w}};
        float a[4] = {a4.x, a4.y, a4.z, a4.w};
#pragma unroll
        for (int i = 0; i < 4; i++) {
            float2 ai = make_float2(a[i], a[i]);
#pragma unroll
            for (int p = 0; p < 4; p++) ffma2(acc2[i][p], ai, wp[p]);
        }
    }

    float4 w3a = *(const float4*)&W3s[j0];
    float4 w3b = *(const float4*)&W3s[j0 + 4];
#pragma unroll
    for (int i = 0; i < 4; i++) {
        int g = base + m0 + i;
        if (g >= n) continue;
        float dd = g_dis[g];
        float o[8] = {acc2[i][0].x, acc2[i][0].y, acc2[i][1].x, acc2[i][1].y,
                      acc2[i][2].x, acc2[i][2].y, acc2[i][3].x, acc2[i][3].y};
#pragma unroll
        for (int j = 0; j < 8; j++) o[j] = fmaxf(o[j] + Bs[j0 + j], 0.0f) * dd;
        float part = o[0] * w3a.x + o[1] * w3a.y + o[2] * w3a.z + o[3] * w3a.w +
                     o[4] * w3b.x + o[5] * w3b.y + o[6] * w3b.z + o[7] * w3b.w;
        atomicAdd(&Ps[m0 + i], part);
    }
    __syncthreads();
    if (t < 128 && base + t < n) g_p2[base + t] = Ps[t];
}

// ------ layer 3: per-node scalar pull of p2 -> red into graph pool ----------
__global__ void __launch_bounds__(256)
k_layer3(const int* __restrict__ batch, int n) {
    int i = blockIdx.x * 256 + threadIdx.x;
    if (i >= n) return;
    float s = g_p2[i];
    int s0 = g_off[i], s1 = g_off[i + 1];
    int k = s0;
    for (; k + 3 < s1; k += 4) {
        float a = g_p2[g_csrc[k]];
        float b = g_p2[g_csrc[k + 1]];
        float c = g_p2[g_csrc[k + 2]];
        float d = g_p2[g_csrc[k + 3]];
        s += (a + b) + (c + d);
    }
    for (; k < s1; k++) s += g_p2[g_csrc[k]];
    red_add_f32(&g_pool1[batch[i]], s * g_dis[i]);
}

// ------------- final: out[g] = pool1/cnt + c0 ; reset state ------------------
__global__ void k_final(float* __restrict__ out, int ng) {
    int i = blockIdx.x * blockDim.x + threadIdx.x;
    if (i < ng) {
        out[i] = g_pool1[i] / fmaxf(g_cnt[i], 1.0f) + g_c0;
        g_pool1[i] = 0.0f;   // reset for next replay
        g_cnt[i] = 0.0f;
    }
}

// ---------------------------------------------------------------------------
extern "C" void kernel_launch(void* const* d_in, const int* in_sizes, int n_in,
                              void* d_out, int out_size) {
    const float* x   = (const float*)d_in[0];
    const int* ei    = (const int*)d_in[1];
    const int* batch = (const int*)d_in[2];
    const float* W1 = (const float*)d_in[3];
    const float* b1 = (const float*)d_in[4];
    const float* W2 = (const float*)d_in[5];
    const float* b2 = (const float*)d_in[6];
    const float* W3 = (const float*)d_in[7];
    const float* b3 = (const float*)d_in[8];
    const float* lw = (const float*)d_in[9];
    const float* lb = (const float*)d_in[10];
    float* out = (float*)d_out;

    int n  = in_sizes[0] / 11;
    int e  = in_sizes[1] / 2;
    int ng = out_size;
    const int* src = ei;
    const int* dst = ei + e;

    int nb  = (n + 1023) / 1024;
    int sb  = (n + 127) / 128;          // staging blocks
    int fb4 = (e + 1023) / 1024;        // fill blocks (4 edges/thread)

    k_deg<<<fb4, 256>>>(dst, e, W3, b3, lw, lb);
    k_scanA<<<nb, 256>>>(n);
    k_scanC<<<nb, 256>>>(batch, n);
    k_stage_fill<<<sb + fb4, 256>>>(x, src, dst, n, e, sb);

    k_layer1<<<(n + 63) / 64, 256>>>(W1, b1, n);
    k_layer2<<<(n + 127) / 128, 256>>>(W2, b2, n);
    k_layer3<<<(n + 255) / 256, 256>>>(batch, n);
    k_final<<<(ng + 255) / 256, 256>>>(out, ng);
}

// round 6
// speedup vs baseline: 2.8094x; 1.0110x over previous
#include <cuda_runtime.h>
#include <cuda_fp16.h>

#define NN 200000
#define NE 1000000
#define NG 4096

// ------------------------- scratch (static device globals) -----------------
static __device__ int            g_degi[NN];     // zeroed inside k_scanC (replay-safe)
static __device__ int            g_off[NN + 1];
static __device__ unsigned short g_rank[NE];     // edge's within-dst rank (from k_deg)
static __device__ int            g_csrc[NE];
static __device__ int            g_bsum[256];
static __device__ float          g_dis[NN];
static __device__ float          g_x16[NN * 16]; // x * dis, padded to 16 (fp32)
static __device__ __half         g_h1h[NN * 64]; // h1 * dis (fp16)
static __device__ float          g_p2[NN];       // (h2 * dis) . w3l  (scalar per node)
static __device__ float          g_pool1[NG];    // zeroed at end of k_final
static __device__ float          g_cnt[NG];      // zeroed at end of k_final
static __device__ float          g_w3l[64];      // W3 @ lin_w
static __device__ float          g_c0;           // b3.lin_w + lin_b

__device__ __forceinline__ void red_add_f32(float* p, float v) {
    asm volatile("red.global.add.f32 [%0], %1;" :: "l"(p), "f"(v) : "memory");
}

// packed f32x2 FMA (Blackwell): acc = a*b + acc
__device__ __forceinline__ void ffma2(float2& acc, float2 a, float2 b) {
    asm("fma.rn.f32x2 %0, %1, %2, %0;"
        : "+l"(*reinterpret_cast<unsigned long long*>(&acc))
        : "l"(*reinterpret_cast<const unsigned long long*>(&a)),
          "l"(*reinterpret_cast<const unsigned long long*>(&b)));
}

// --------- degree histogram w/ rank stash + (block 0) prep w3l/c0 -----------
__global__ void k_deg(const int* __restrict__ dst, int e,
                      const float* __restrict__ W3, const float* __restrict__ b3,
                      const float* __restrict__ lw, const float* __restrict__ lb) {
    if (blockIdx.x == 0 && threadIdx.x < 64) {
        int t = threadIdx.x;
        float s = 0.0f;
        for (int j = 0; j < 64; j++) s += W3[t * 64 + j] * lw[j];
        g_w3l[t] = s;
        if (t == 0) {
            float c = lb[0];
            for (int j = 0; j < 64; j++) c += b3[j] * lw[j];
            g_c0 = c;
        }
    }
    int i = (blockIdx.x * 256 + threadIdx.x) * 4;
    if (i + 3 < e) {
        int4 d4 = *(const int4*)&dst[i];
        ushort4 r4;
        r4.x = (unsigned short)atomicAdd(&g_degi[d4.x], 1);
        r4.y = (unsigned short)atomicAdd(&g_degi[d4.y], 1);
        r4.z = (unsigned short)atomicAdd(&g_degi[d4.z], 1);
        r4.w = (unsigned short)atomicAdd(&g_degi[d4.w], 1);
        *(ushort4*)&g_rank[i] = r4;
    } else {
        for (; i < e; i++)
            g_rank[i] = (unsigned short)atomicAdd(&g_degi[dst[i]], 1);
    }
}

// -------- scanA: per-1024-chunk degree sums ----------------------------------
__global__ void k_scanA(int n) {
    __shared__ int ws[8];
    int b = blockIdx.x, t = threadIdx.x;
    int base = b * 1024;
    int sum = 0;
    for (int i = t; i < 1024; i += 256) {
        int g = base + i;
        if (g < n) sum += g_degi[g];
    }
#pragma unroll
    for (int o = 16; o; o >>= 1) sum += __shfl_down_sync(~0u, sum, o);
    if ((t & 31) == 0) ws[t >> 5] = sum;
    __syncthreads();
    if (t == 0) {
        int s = 0;
#pragma unroll
        for (int w = 0; w < 8; w++) s += ws[w];
        g_bsum[b] = s;
    }
}

// -------- scanC: offsets + dis + graph counts --------------------------------
__global__ void k_scanC(const int* __restrict__ batch, int n) {
    __shared__ int ws[8];
    __shared__ int s_boff;
    int b = blockIdx.x, t = threadIdx.x;

    {   // block offset = prefix of chunk sums
        int p = (t < b) ? g_bsum[t] : 0;
#pragma unroll
        for (int o = 16; o; o >>= 1) p += __shfl_down_sync(~0u, p, o);
        if ((t & 31) == 0) ws[t >> 5] = p;
        __syncthreads();
        if (t == 0) {
            int s = 0;
#pragma unroll
            for (int w = 0; w < 8; w++) s += ws[w];
            s_boff = s;
        }
        __syncthreads();
    }

    int base = b * 1024 + t * 4;
    int d[4];
#pragma unroll
    for (int i = 0; i < 4; i++) {
        int g = base + i;
        d[i] = (g < n) ? g_degi[g] : 0;
        if (g < n) g_degi[g] = 0;  // reset for next replay
    }
    int tot = d[0] + d[1] + d[2] + d[3];
    int inc = tot;
#pragma unroll
    for (int o = 1; o < 32; o <<= 1) {
        int u = __shfl_up_sync(~0u, inc, o);
        if ((t & 31) >= o) inc += u;
    }
    if ((t & 31) == 31) ws[t >> 5] = inc;
    __syncthreads();
    if (t < 8) {
        int w = ws[t];
#pragma unroll
        for (int o = 1; o < 8; o <<= 1) {
            int u = __shfl_up_sync(0xFFu, w, o);
            if (t >= o) w += u;
        }
        ws[t] = w;
    }
    __syncthreads();
    int off = inc - tot + ((t >= 32) ? ws[(t >> 5) - 1] : 0) + s_boff;

#pragma unroll
    for (int i = 0; i < 4; i++) {
        int g = base + i;
        if (g < n) {
            g_off[g] = off;
            g_dis[g] = rsqrtf((float)(d[i] + 1));
            if (g == n - 1) g_off[n] = off + d[i];
            off += d[i];
        }
    }
    // graph node counts (dedup across 4 consecutive batch-sorted nodes)
    int cb = -1; float cc = 0.0f;
#pragma unroll
    for (int i = 0; i < 4; i++) {
        int g = base + i;
        if (g >= n) continue;
        int bb = batch[g];
        if (bb == cb) cc += 1.0f;
        else {
            if (cb >= 0) atomicAdd(&g_cnt[cb], cc);
            cb = bb; cc = 1.0f;
        }
    }
    if (cb >= 0) atomicAdd(&g_cnt[cb], cc);
}

// --------- fused: x staging (coalesced) + CSR fill (atomic-free) -------------
__global__ void __launch_bounds__(256)
k_stage_fill(const float* __restrict__ x, const int* __restrict__ src,
             const int* __restrict__ dst, int n, int e, int sb) {
    int t = threadIdx.x;
    if ((int)blockIdx.x < sb) {
        __shared__ float xs[128 * 11];
        int nbase = blockIdx.x * 128;
        int lim = min(128, n - nbase) * 11;
        for (int i = t; i < lim; i += 256) xs[i] = x[nbase * 11 + i];
        __syncthreads();
        for (int idx = t; idx < 512; idx += 256) {
            int m = idx >> 2, q = idx & 3;
            int g = nbase + m;
            if (g >= n) break;
            float dis = g_dis[g];
            float4 v;
            int c = q * 4;
            v.x = (c + 0 < 11) ? xs[m * 11 + c + 0] * dis : 0.0f;
            v.y = (c + 1 < 11) ? xs[m * 11 + c + 1] * dis : 0.0f;
            v.z = (c + 2 < 11) ? xs[m * 11 + c + 2] * dis : 0.0f;
            v.w = (c + 3 < 11) ? xs[m * 11 + c + 3] * dis : 0.0f;
            *(float4*)&g_x16[g * 16 + c] = v;
        }
    } else {
        // atomic-free fill: slot = off[dst] + stashed rank
        int i = ((blockIdx.x - sb) * 256 + t) * 4;
        if (i + 3 < e) {
            int4 s4 = *(const int4*)&src[i];
            int4 d4 = *(const int4*)&dst[i];
            ushort4 r4 = *(const ushort4*)&g_rank[i];
            g_csrc[g_off[d4.x] + r4.x] = s4.x;
            g_csrc[g_off[d4.y] + r4.y] = s4.y;
            g_csrc[g_off[d4.z] + r4.z] = s4.z;
            g_csrc[g_off[d4.w] + r4.w] = s4.w;
        } else {
            for (; i < e; i++)
                g_csrc[g_off[dst[i]] + g_rank[i]] = src[i];
        }
    }
}

// ------------- layer 1 fused: pull(16-dim x~) + GEMM K=16 -> h1~ (fp16) ------
__global__ void __launch_bounds__(256)
k_layer1(const float* __restrict__ W, const float* __restrict__ bias, int n) {
    __shared__ float Am[16 * 73];
    __shared__ float Ws[16 * 64];
    __shared__ float Bs[64];
    const int t = threadIdx.x;
    const int base = blockIdx.x * 64;

    for (int i = t; i < 16 * 64; i += 256) Ws[i] = (i < 11 * 64) ? W[i] : 0.0f;
    if (t < 64) Bs[t] = bias[t];

    {   // pull: 4 lanes/node, 64 nodes/block
        int lane = t & 3, slot = t >> 2;
        int node = base + slot;
        float4 acc = make_float4(0.f, 0.f, 0.f, 0.f);
        float dd = 0.0f;
        if (node < n) {
            acc = *(const float4*)&g_x16[node * 16 + lane * 4];
            int s0 = g_off[node], s1 = g_off[node + 1];
            int k = s0;
            for (; k + 3 < s1; k += 4) {
                int a = g_csrc[k], b2i = g_csrc[k + 1], c = g_csrc[k + 2], d = g_csrc[k + 3];
                float4 va = *(const float4*)&g_x16[a * 16 + lane * 4];
                float4 vb = *(const float4*)&g_x16[b2i * 16 + lane * 4];
                float4 vc = *(const float4*)&g_x16[c * 16 + lane * 4];
                float4 vd = *(const float4*)&g_x16[d * 16 + lane * 4];
                acc.x += (va.x + vb.x) + (vc.x + vd.x);
                acc.y += (va.y + vb.y) + (vc.y + vd.y);
                acc.z += (va.z + vb.z) + (vc.z + vd.z);
                acc.w += (va.w + vb.w) + (vc.w + vd.w);
            }
            for (; k < s1; k++) {
                int a = g_csrc[k];
                float4 va = *(const float4*)&g_x16[a * 16 + lane * 4];
                acc.x += va.x; acc.y += va.y; acc.z += va.z; acc.w += va.w;
            }
            dd = g_dis[node];
        }
        Am[(lane * 4 + 0) * 73 + slot] = acc.x * dd;
        Am[(lane * 4 + 1) * 73 + slot] = acc.y * dd;
        Am[(lane * 4 + 2) * 73 + slot] = acc.z * dd;
        Am[(lane * 4 + 3) * 73 + slot] = acc.w * dd;
    }
    __syncthreads();

    const int m0 = (t & 31) * 2;
    const int j0 = (t >> 5) * 8;
    float2 acc2[2][4];
#pragma unroll
    for (int i = 0; i < 2; i++)
#pragma unroll
        for (int p = 0; p < 4; p++) acc2[i][p] = make_float2(0.f, 0.f);

#pragma unroll
    for (int k = 0; k < 16; k++) {
        float a0 = Am[k * 73 + m0];
        float a1 = Am[k * 73 + m0 + 1];
        float4 w0 = *(const float4*)&Ws[k * 64 + j0];
        float4 w1 = *(const float4*)&Ws[k * 64 + j0 + 4];
        float2 wp[4] = {{w0.x, w0.y}, {w0.z, w0.w}, {w1.x, w1.y}, {w1.z, w1.w}};
        float2 A0 = make_float2(a0, a0), A1 = make_float2(a1, a1);
#pragma unroll
        for (int p = 0; p < 4; p++) { ffma2(acc2[0][p], A0, wp[p]); ffma2(acc2[1][p], A1, wp[p]); }
    }

#pragma unroll
    for (int i = 0; i < 2; i++) {
        int g = base + m0 + i;
        if (g >= n) continue;
        float dd = g_dis[g];
        float o[8] = {acc2[i][0].x, acc2[i][0].y, acc2[i][1].x, acc2[i][1].y,
                      acc2[i][2].x, acc2[i][2].y, acc2[i][3].x, acc2[i][3].y};
#pragma unroll
        for (int j = 0; j < 8; j++) o[j] = fmaxf(o[j] + Bs[j0 + j], 0.0f) * dd;
        __half2 h[4];
#pragma unroll
        for (int q = 0; q < 4; q++) h[q] = __floats2half2_rn(o[q * 2], o[q * 2 + 1]);
        *(uint4*)&g_h1h[g * 64 + j0] = *(uint4*)h;
    }
}

// -- layer 2 fused: pull(fp16 h1~) + GEMM K=64 -> p2 scalar; 128-node tile ----
__global__ void __launch_bounds__(256)
k_layer2(const float* __restrict__ W, const float* __restrict__ bias, int n) {
    __shared__ float Am[64 * 136];
    __shared__ float Ws[64 * 64];
    __shared__ float Bs[64];
    __shared__ float W3s[64];
    __shared__ float Ps[128];
    const int t = threadIdx.x;
    const int base = blockIdx.x * 128;

    for (int i = t * 4; i < 64 * 64; i += 1024)
        *(float4*)&Ws[i] = *(const float4*)&W[i];
    if (t < 64) { Bs[t] = bias[t]; W3s[t] = g_w3l[t]; }
    if (t < 128) Ps[t] = 0.0f;

    {   // pull: 8 lanes/node (fp16 rows, 16B each), 4 serial nodes per thread
        int lane = t & 7, slot = t >> 3;   // 32 slots
#pragma unroll
        for (int s = 0; s < 4; s++) {
            int node = base + slot + 32 * s;
            float acc[8] = {0, 0, 0, 0, 0, 0, 0, 0};
            float dd = 0.0f;
            if (node < n) {
                uint4 r = *(const uint4*)&g_h1h[node * 64 + lane * 8];
                __half2* hp = (__half2*)&r;
#pragma unroll
                for (int q = 0; q < 4; q++) {
                    float2 f = __half22float2(hp[q]);
                    acc[q * 2] = f.x; acc[q * 2 + 1] = f.y;
                }
                int s0 = g_off[node], s1 = g_off[node + 1];
                int k = s0;
                for (; k + 1 < s1; k += 2) {
                    int a = g_csrc[k], b2i = g_csrc[k + 1];
                    uint4 ra = *(const uint4*)&g_h1h[a * 64 + lane * 8];
                    uint4 rb = *(const uint4*)&g_h1h[b2i * 64 + lane * 8];
                    __half2* pa = (__half2*)&ra;
                    __half2* pb = (__half2*)&rb;
#pragma unroll
                    for (int q = 0; q < 4; q++) {
                        float2 fa = __half22float2(pa[q]);
                        float2 fb = __half22float2(pb[q]);
                        acc[q * 2]     += fa.x + fb.x;
                        acc[q * 2 + 1] += fa.y + fb.y;
                    }
                }
                if (k < s1) {
                    int a = g_csrc[k];
                    uint4 ra = *(const uint4*)&g_h1h[a * 64 + lane * 8];
                    __half2* pa = (__half2*)&ra;
#pragma unroll
                    for (int q = 0; q < 4; q++) {
                        float2 fa = __half22float2(pa[q]);
                        acc[q * 2] += fa.x; acc[q * 2 + 1] += fa.y;
                    }
                }
                dd = g_dis[node];
            }
            int m = slot + 32 * s;
#pragma unroll
            for (int q = 0; q < 8; q++)
                Am[(lane * 8 + q) * 136 + m] = acc[q] * dd;
        }
    }
    __syncthreads();

    // GEMM: 4 nodes x 8 outs per thread; per-warp uniform j0 (broadcast W reads)
    const int m0 = (t & 31) * 4;
    const int j0 = (t >> 5) * 8;
    float2 acc2[4][4];
#pragma unroll
    for (int i = 0; i < 4; i++)
#pragma unroll
        for (int p = 0; p < 4; p++) acc2[i][p] = make_float2(0.f, 0.f);

#pragma unroll 8
    for (int k = 0; k < 64; k++) {
        float4 a4 = *(const float4*)&Am[k * 136 + m0];
        float4 w0 = *(const float4*)&Ws[k * 64 + j0];
        float4 w1 = *(const float4*)&Ws[k * 64 + j0 + 4];
        float2 wp[4] = {{w0.x, w0.y}, {w0.z, w0.w}, {w1.x, w1.y}, {w1.z, w1.w}};
        float a[4] = {a4.x, a4.y, a4.z, a4.w};
#pragma unroll
        for (int i = 0; i < 4; i++) {
            float2 ai = make_float2(a[i], a[i]);
#pragma unroll
            for (int p = 0; p < 4; p++) ffma2(acc2[i][p], ai, wp[p]);
        }
    }

    float4 w3a = *(const float4*)&W3s[j0];
    float4 w3b = *(const float4*)&W3s[j0 + 4];
#pragma unroll
    for (int i = 0; i < 4; i++) {
        int g = base + m0 + i;
        if (g >= n) continue;
        float dd = g_dis[g];
        float o[8] = {acc2[i][0].x, acc2[i][0].y, acc2[i][1].x, acc2[i][1].y,
                      acc2[i][2].x, acc2[i][2].y, acc2[i][3].x, acc2[i][3].y};
#pragma unroll
        for (int j = 0; j < 8; j++) o[j] = fmaxf(o[j] + Bs[j0 + j], 0.0f) * dd;
        float part = o[0] * w3a.x + o[1] * w3a.y + o[2] * w3a.z + o[3] * w3a.w +
                     o[4] * w3b.x + o[5] * w3b.y + o[6] * w3b.z + o[7] * w3b.w;
        atomicAdd(&Ps[m0 + i], part);
    }
    __syncthreads();
    if (t < 128 && base + t < n) g_p2[base + t] = Ps[t];
}

// ------ layer 3: per-node scalar pull of p2 -> red into graph pool ----------
__global__ void __launch_bounds__(256)
k_layer3(const int* __restrict__ batch, int n) {
    int i = blockIdx.x * 256 + threadIdx.x;
    if (i >= n) return;
    float s = g_p2[i];
    int s0 = g_off[i], s1 = g_off[i + 1];
    int k = s0;
    for (; k + 3 < s1; k += 4) {
        float a = g_p2[g_csrc[k]];
        float b = g_p2[g_csrc[k + 1]];
        float c = g_p2[g_csrc[k + 2]];
        float d = g_p2[g_csrc[k + 3]];
        s += (a + b) + (c + d);
    }
    for (; k < s1; k++) s += g_p2[g_csrc[k]];
    red_add_f32(&g_pool1[batch[i]], s * g_dis[i]);
}

// ------------- final: out[g] = pool1/cnt + c0 ; reset state ------------------
__global__ void k_final(float* __restrict__ out, int ng) {
    int i = blockIdx.x * blockDim.x + threadIdx.x;
    if (i < ng) {
        out[i] = g_pool1[i] / fmaxf(g_cnt[i], 1.0f) + g_c0;
        g_pool1[i] = 0.0f;   // reset for next replay
        g_cnt[i] = 0.0f;
    }
}

// ---------------------------------------------------------------------------
extern "C" void kernel_launch(void* const* d_in, const int* in_sizes, int n_in,
                              void* d_out, int out_size) {
    const float* x   = (const float*)d_in[0];
    const int* ei    = (const int*)d_in[1];
    const int* batch = (const int*)d_in[2];
    const float* W1 = (const float*)d_in[3];
    const float* b1 = (const float*)d_in[4];
    const float* W2 = (const float*)d_in[5];
    const float* b2 = (const float*)d_in[6];
    const float* W3 = (const float*)d_in[7];
    const float* b3 = (const float*)d_in[8];
    const float* lw = (const float*)d_in[9];
    const float* lb = (const float*)d_in[10];
    float* out = (float*)d_out;

    int n  = in_sizes[0] / 11;
    int e  = in_sizes[1] / 2;
    int ng = out_size;
    const int* src = ei;
    const int* dst = ei + e;

    int nb  = (n + 1023) / 1024;
    int sb  = (n + 127) / 128;          // staging blocks
    int fb4 = (e + 1023) / 1024;        // fill blocks (4 edges/thread)

    k_deg<<<fb4, 256>>>(dst, e, W3, b3, lw, lb);
    k_scanA<<<nb, 256>>>(n);
    k_scanC<<<nb, 256>>>(batch, n);
    k_stage_fill<<<sb + fb4, 256>>>(x, src, dst, n, e, sb);

    k_layer1<<<(n + 63) / 64, 256>>>(W1, b1, n);
    k_layer2<<<(n + 127) / 128, 256>>>(W2, b2, n);
    k_layer3<<<(n + 255) / 256, 256>>>(batch, n);
    k_final<<<(ng + 255) / 256, 256>>>(out, ng);
}

// round 7
// speedup vs baseline: 3.3495x; 1.1923x over previous
#include <cuda_runtime.h>
#include <cuda_fp16.h>

#define NN 200000
#define NE 1000000
#define NG 4096

// ------------------------- scratch (static device globals) -----------------
static __device__ int            g_degi[NN];     // zeroed inside k_scanC (replay-safe)
static __device__ int            g_off[NN + 1];
static __device__ unsigned short g_rank[NE];     // edge's within-dst rank (from k_deg)
static __device__ int            g_csrc[NE];
static __device__ int            g_bsum[256];
static __device__ float          g_dis[NN];
static __device__ float          g_x16[NN * 16]; // x * dis, padded to 16 (fp32)
static __device__ __half         g_h1h[NN * 64]; // h1 * dis (fp16)
static __device__ float          g_p2[NN];       // (h2 * dis) . w3l  (scalar per node)
static __device__ float          g_pool1[NG];    // zeroed at end of k_final
static __device__ float          g_cnt[NG];      // zeroed at end of k_final
static __device__ float          g_w3l[64];      // W3 @ lin_w
static __device__ float          g_c0;           // b3.lin_w + lin_b

__device__ __forceinline__ void red_add_f32(float* p, float v) {
    asm volatile("red.global.add.f32 [%0], %1;" :: "l"(p), "f"(v) : "memory");
}

// packed f32x2 FMA (Blackwell): acc = a*b + acc
__device__ __forceinline__ void ffma2(float2& acc, float2 a, float2 b) {
    asm("fma.rn.f32x2 %0, %1, %2, %0;"
        : "+l"(*reinterpret_cast<unsigned long long*>(&acc))
        : "l"(*reinterpret_cast<const unsigned long long*>(&a)),
          "l"(*reinterpret_cast<const unsigned long long*>(&b)));
}

// m16n8k16 fp16 MMA, fp32 accum
__device__ __forceinline__ void mma16816(float* d, unsigned a0, unsigned a1,
                                         unsigned a2, unsigned a3,
                                         unsigned b0, unsigned b1) {
    asm volatile(
        "mma.sync.aligned.m16n8k16.row.col.f32.f16.f16.f32 "
        "{%0,%1,%2,%3}, {%4,%5,%6,%7}, {%8,%9}, {%0,%1,%2,%3};"
        : "+f"(d[0]), "+f"(d[1]), "+f"(d[2]), "+f"(d[3])
        : "r"(a0), "r"(a1), "r"(a2), "r"(a3), "r"(b0), "r"(b1));
}

// --------- degree histogram w/ rank stash + (block 0) prep w3l/c0 -----------
__global__ void k_deg(const int* __restrict__ dst, int e,
                      const float* __restrict__ W3, const float* __restrict__ b3,
                      const float* __restrict__ lw, const float* __restrict__ lb) {
    if (blockIdx.x == 0 && threadIdx.x < 64) {
        int t = threadIdx.x;
        float s = 0.0f;
        for (int j = 0; j < 64; j++) s += W3[t * 64 + j] * lw[j];
        g_w3l[t] = s;
        if (t == 0) {
            float c = lb[0];
            for (int j = 0; j < 64; j++) c += b3[j] * lw[j];
            g_c0 = c;
        }
    }
    int i = (blockIdx.x * 256 + threadIdx.x) * 4;
    if (i + 3 < e) {
        int4 d4 = *(const int4*)&dst[i];
        ushort4 r4;
        r4.x = (unsigned short)atomicAdd(&g_degi[d4.x], 1);
        r4.y = (unsigned short)atomicAdd(&g_degi[d4.y], 1);
        r4.z = (unsigned short)atomicAdd(&g_degi[d4.z], 1);
        r4.w = (unsigned short)atomicAdd(&g_degi[d4.w], 1);
        *(ushort4*)&g_rank[i] = r4;
    } else {
        for (; i < e; i++)
            g_rank[i] = (unsigned short)atomicAdd(&g_degi[dst[i]], 1);
    }
}

// -------- scanA: per-1024-chunk degree sums ----------------------------------
__global__ void k_scanA(int n) {
    __shared__ int ws[8];
    int b = blockIdx.x, t = threadIdx.x;
    int base = b * 1024;
    int sum = 0;
    for (int i = t; i < 1024; i += 256) {
        int g = base + i;
        if (g < n) sum += g_degi[g];
    }
#pragma unroll
    for (int o = 16; o; o >>= 1) sum += __shfl_down_sync(~0u, sum, o);
    if ((t & 31) == 0) ws[t >> 5] = sum;
    __syncthreads();
    if (t == 0) {
        int s = 0;
#pragma unroll
        for (int w = 0; w < 8; w++) s += ws[w];
        g_bsum[b] = s;
    }
}

// -------- scanC: offsets + dis + graph counts --------------------------------
__global__ void k_scanC(const int* __restrict__ batch, int n) {
    __shared__ int ws[8];
    __shared__ int s_boff;
    int b = blockIdx.x, t = threadIdx.x;

    {   // block offset = prefix of chunk sums
        int p = (t < b) ? g_bsum[t] : 0;
#pragma unroll
        for (int o = 16; o; o >>= 1) p += __shfl_down_sync(~0u, p, o);
        if ((t & 31) == 0) ws[t >> 5] = p;
        __syncthreads();
        if (t == 0) {
            int s = 0;
#pragma unroll
            for (int w = 0; w < 8; w++) s += ws[w];
            s_boff = s;
        }
        __syncthreads();
    }

    int base = b * 1024 + t * 4;
    int d[4];
#pragma unroll
    for (int i = 0; i < 4; i++) {
        int g = base + i;
        d[i] = (g < n) ? g_degi[g] : 0;
        if (g < n) g_degi[g] = 0;  // reset for next replay
    }
    int tot = d[0] + d[1] + d[2] + d[3];
    int inc = tot;
#pragma unroll
    for (int o = 1; o < 32; o <<= 1) {
        int u = __shfl_up_sync(~0u, inc, o);
        if ((t & 31) >= o) inc += u;
    }
    if ((t & 31) == 31) ws[t >> 5] = inc;
    __syncthreads();
    if (t < 8) {
        int w = ws[t];
#pragma unroll
        for (int o = 1; o < 8; o <<= 1) {
            int u = __shfl_up_sync(0xFFu, w, o);
            if (t >= o) w += u;
        }
        ws[t] = w;
    }
    __syncthreads();
    int off = inc - tot + ((t >= 32) ? ws[(t >> 5) - 1] : 0) + s_boff;

#pragma unroll
    for (int i = 0; i < 4; i++) {
        int g = base + i;
        if (g < n) {
            g_off[g] = off;
            g_dis[g] = rsqrtf((float)(d[i] + 1));
            if (g == n - 1) g_off[n] = off + d[i];
            off += d[i];
        }
    }
    // graph node counts (dedup across 4 consecutive batch-sorted nodes)
    int cb = -1; float cc = 0.0f;
#pragma unroll
    for (int i = 0; i < 4; i++) {
        int g = base + i;
        if (g >= n) continue;
        int bb = batch[g];
        if (bb == cb) cc += 1.0f;
        else {
            if (cb >= 0) atomicAdd(&g_cnt[cb], cc);
            cb = bb; cc = 1.0f;
        }
    }
    if (cb >= 0) atomicAdd(&g_cnt[cb], cc);
}

// --------- fused: x staging (coalesced) + CSR fill (atomic-free) -------------
__global__ void __launch_bounds__(256)
k_stage_fill(const float* __restrict__ x, const int* __restrict__ src,
             const int* __restrict__ dst, int n, int e, int sb) {
    int t = threadIdx.x;
    if ((int)blockIdx.x < sb) {
        __shared__ float xs[128 * 11];
        int nbase = blockIdx.x * 128;
        int lim = min(128, n - nbase) * 11;
        for (int i = t; i < lim; i += 256) xs[i] = x[nbase * 11 + i];
        __syncthreads();
        for (int idx = t; idx < 512; idx += 256) {
            int m = idx >> 2, q = idx & 3;
            int g = nbase + m;
            if (g >= n) break;
            float dis = g_dis[g];
            float4 v;
            int c = q * 4;
            v.x = (c + 0 < 11) ? xs[m * 11 + c + 0] * dis : 0.0f;
            v.y = (c + 1 < 11) ? xs[m * 11 + c + 1] * dis : 0.0f;
            v.z = (c + 2 < 11) ? xs[m * 11 + c + 2] * dis : 0.0f;
            v.w = (c + 3 < 11) ? xs[m * 11 + c + 3] * dis : 0.0f;
            *(float4*)&g_x16[g * 16 + c] = v;
        }
    } else {
        // atomic-free fill: slot = off[dst] + stashed rank
        int i = ((blockIdx.x - sb) * 256 + t) * 4;
        if (i + 3 < e) {
            int4 s4 = *(const int4*)&src[i];
            int4 d4 = *(const int4*)&dst[i];
            ushort4 r4 = *(const ushort4*)&g_rank[i];
            g_csrc[g_off[d4.x] + r4.x] = s4.x;
            g_csrc[g_off[d4.y] + r4.y] = s4.y;
            g_csrc[g_off[d4.z] + r4.z] = s4.z;
            g_csrc[g_off[d4.w] + r4.w] = s4.w;
        } else {
            for (; i < e; i++)
                g_csrc[g_off[dst[i]] + g_rank[i]] = src[i];
        }
    }
}

// ------------- layer 1 fused: pull(16-dim x~) + GEMM K=16 -> h1~ (fp16) ------
__global__ void __launch_bounds__(256)
k_layer1(const float* __restrict__ W, const float* __restrict__ bias, int n) {
    __shared__ float Am[16 * 73];
    __shared__ float Ws[16 * 64];
    __shared__ float Bs[64];
    const int t = threadIdx.x;
    const int base = blockIdx.x * 64;

    for (int i = t; i < 16 * 64; i += 256) Ws[i] = (i < 11 * 64) ? W[i] : 0.0f;
    if (t < 64) Bs[t] = bias[t];

    {   // pull: 4 lanes/node, 64 nodes/block
        int lane = t & 3, slot = t >> 2;
        int node = base + slot;
        float4 acc = make_float4(0.f, 0.f, 0.f, 0.f);
        float dd = 0.0f;
        if (node < n) {
            acc = *(const float4*)&g_x16[node * 16 + lane * 4];
            int s0 = g_off[node], s1 = g_off[node + 1];
            int k = s0;
            for (; k + 3 < s1; k += 4) {
                int a = g_csrc[k], b2i = g_csrc[k + 1], c = g_csrc[k + 2], d = g_csrc[k + 3];
                float4 va = *(const float4*)&g_x16[a * 16 + lane * 4];
                float4 vb = *(const float4*)&g_x16[b2i * 16 + lane * 4];
                float4 vc = *(const float4*)&g_x16[c * 16 + lane * 4];
                float4 vd = *(const float4*)&g_x16[d * 16 + lane * 4];
                acc.x += (va.x + vb.x) + (vc.x + vd.x);
                acc.y += (va.y + vb.y) + (vc.y + vd.y);
                acc.z += (va.z + vb.z) + (vc.z + vd.z);
                acc.w += (va.w + vb.w) + (vc.w + vd.w);
            }
            for (; k < s1; k++) {
                int a = g_csrc[k];
                float4 va = *(const float4*)&g_x16[a * 16 + lane * 4];
                acc.x += va.x; acc.y += va.y; acc.z += va.z; acc.w += va.w;
            }
            dd = g_dis[node];
        }
        Am[(lane * 4 + 0) * 73 + slot] = acc.x * dd;
        Am[(lane * 4 + 1) * 73 + slot] = acc.y * dd;
        Am[(lane * 4 + 2) * 73 + slot] = acc.z * dd;
        Am[(lane * 4 + 3) * 73 + slot] = acc.w * dd;
    }
    __syncthreads();

    const int m0 = (t & 31) * 2;
    const int j0 = (t >> 5) * 8;
    float2 acc2[2][4];
#pragma unroll
    for (int i = 0; i < 2; i++)
#pragma unroll
        for (int p = 0; p < 4; p++) acc2[i][p] = make_float2(0.f, 0.f);

#pragma unroll
    for (int k = 0; k < 16; k++) {
        float a0 = Am[k * 73 + m0];
        float a1 = Am[k * 73 + m0 + 1];
        float4 w0 = *(const float4*)&Ws[k * 64 + j0];
        float4 w1 = *(const float4*)&Ws[k * 64 + j0 + 4];
        float2 wp[4] = {{w0.x, w0.y}, {w0.z, w0.w}, {w1.x, w1.y}, {w1.z, w1.w}};
        float2 A0 = make_float2(a0, a0), A1 = make_float2(a1, a1);
#pragma unroll
        for (int p = 0; p < 4; p++) { ffma2(acc2[0][p], A0, wp[p]); ffma2(acc2[1][p], A1, wp[p]); }
    }

#pragma unroll
    for (int i = 0; i < 2; i++) {
        int g = base + m0 + i;
        if (g >= n) continue;
        float dd = g_dis[g];
        float o[8] = {acc2[i][0].x, acc2[i][0].y, acc2[i][1].x, acc2[i][1].y,
                      acc2[i][2].x, acc2[i][2].y, acc2[i][3].x, acc2[i][3].y};
#pragma unroll
        for (int j = 0; j < 8; j++) o[j] = fmaxf(o[j] + Bs[j0 + j], 0.0f) * dd;
        __half2 h[4];
#pragma unroll
        for (int q = 0; q < 4; q++) h[q] = __floats2half2_rn(o[q * 2], o[q * 2 + 1]);
        *(uint4*)&g_h1h[g * 64 + j0] = *(uint4*)h;
    }
}

// -- layer 2: fp16 pull (HADD2) + tensor-core GEMM (m16n8k16) -> p2 scalar ----
__global__ void __launch_bounds__(256)
k_layer2(const float* __restrict__ W, const float* __restrict__ bias, int n) {
    __shared__ __half Amh[128 * 72];   // node-major, stride 72 halves
    __shared__ __half Wt[64 * 72];     // n-major transposed W2 (fp16), stride 72
    __shared__ float  Bs[64];
    __shared__ float  W3s[64];
    const int t = threadIdx.x;
    const int base = blockIdx.x * 128;

    // stage W2 -> fp16 transposed (n-major) + bias + w3l
    for (int i = t; i < 64 * 64; i += 256) {
        int k = i >> 6, nn2 = i & 63;
        Wt[nn2 * 72 + k] = __float2half(W[i]);
    }
    if (t < 64) { Bs[t] = bias[t]; W3s[t] = g_w3l[t]; }

    {   // pull: 8 lanes/node (16B of fp16 each), 4 serial nodes per thread,
        // neighbor accumulation entirely in fp16 (HADD2, pairwise)
        int lane = t & 7, slot = t >> 3;   // 32 slots
#pragma unroll
        for (int s = 0; s < 4; s++) {
            int node = base + slot + 32 * s;
            __half2 acc[4];
#pragma unroll
            for (int q = 0; q < 4; q++) acc[q] = __float2half2_rn(0.0f);
            uint4 selfr = make_uint4(0, 0, 0, 0);
            float dd = 0.0f;
            if (node < n) {
                selfr = *(const uint4*)&g_h1h[node * 64 + lane * 8];
                int s0 = g_off[node], s1 = g_off[node + 1];
                int k = s0;
                for (; k + 1 < s1; k += 2) {
                    int a = g_csrc[k], b2i = g_csrc[k + 1];
                    uint4 ra = *(const uint4*)&g_h1h[a * 64 + lane * 8];
                    uint4 rb = *(const uint4*)&g_h1h[b2i * 64 + lane * 8];
                    __half2* pa = (__half2*)&ra;
                    __half2* pb = (__half2*)&rb;
#pragma unroll
                    for (int q = 0; q < 4; q++)
                        acc[q] = __hadd2(acc[q], __hadd2(pa[q], pb[q]));
                }
                if (k < s1) {
                    int a = g_csrc[k];
                    uint4 ra = *(const uint4*)&g_h1h[a * 64 + lane * 8];
                    __half2* pa = (__half2*)&ra;
#pragma unroll
                    for (int q = 0; q < 4; q++) acc[q] = __hadd2(acc[q], pa[q]);
                }
                dd = g_dis[node];
            }
            int m = slot + 32 * s;
            __half2* sp = (__half2*)&selfr;
#pragma unroll
            for (int q = 0; q < 4; q++) {
                float2 fa = __half22float2(acc[q]);
                float2 fs = __half22float2(sp[q]);
                *(__half2*)&Amh[m * 72 + lane * 8 + q * 2] =
                    __floats2half2_rn((fs.x + fa.x) * dd, (fs.y + fa.y) * dd);
            }
        }
    }
    __syncthreads();

    // tensor-core GEMM: warp w owns m-tile [w*16, w*16+16), all 8 n-tiles, K=64
    const int lane = t & 31, w = t >> 5;
    const int g2 = lane >> 2, qd = lane & 3;
    float d[8][4];
#pragma unroll
    for (int nt = 0; nt < 8; nt++)
#pragma unroll
        for (int q = 0; q < 4; q++) d[nt][q] = 0.0f;

#pragma unroll
    for (int kstep = 0; kstep < 4; kstep++) {
        int kc = qd * 2 + kstep * 16;
        int row = w * 16 + g2;
        unsigned a0 = *(const unsigned*)&Amh[row * 72 + kc];
        unsigned a1 = *(const unsigned*)&Amh[(row + 8) * 72 + kc];
        unsigned a2 = *(const unsigned*)&Amh[row * 72 + kc + 8];
        unsigned a3 = *(const unsigned*)&Amh[(row + 8) * 72 + kc + 8];
#pragma unroll
        for (int nt = 0; nt < 8; nt++) {
            unsigned b0 = *(const unsigned*)&Wt[(nt * 8 + g2) * 72 + kc];
            unsigned b1 = *(const unsigned*)&Wt[(nt * 8 + g2) * 72 + kc + 8];
            mma16816(d[nt], a0, a1, a2, a3, b0, b1);
        }
    }

    // epilogue: bias+relu, dot with w3l, quad-reduce -> p2
    float part0 = 0.0f, part1 = 0.0f;
#pragma unroll
    for (int nt = 0; nt < 8; nt++) {
        int col = nt * 8 + qd * 2;
        float b0 = Bs[col], b1 = Bs[col + 1];
        float w0 = W3s[col], w1 = W3s[col + 1];
        part0 += fmaxf(d[nt][0] + b0, 0.0f) * w0 + fmaxf(d[nt][1] + b1, 0.0f) * w1;
        part1 += fmaxf(d[nt][2] + b0, 0.0f) * w0 + fmaxf(d[nt][3] + b1, 0.0f) * w1;
    }
    part0 += __shfl_xor_sync(~0u, part0, 1);
    part0 += __shfl_xor_sync(~0u, part0, 2);
    part1 += __shfl_xor_sync(~0u, part1, 1);
    part1 += __shfl_xor_sync(~0u, part1, 2);
    if (qd == 0) {
        int node0 = base + w * 16 + g2;
        int node1 = node0 + 8;
        if (node0 < n) g_p2[node0] = part0 * g_dis[node0];
        if (node1 < n) g_p2[node1] = part1 * g_dis[node1];
    }
}

// ------ layer 3: per-node scalar pull of p2 -> red into graph pool ----------
__global__ void __launch_bounds__(256)
k_layer3(const int* __restrict__ batch, int n) {
    int i = blockIdx.x * 256 + threadIdx.x;
    if (i >= n) return;
    float s = g_p2[i];
    int s0 = g_off[i], s1 = g_off[i + 1];
    int k = s0;
    for (; k + 3 < s1; k += 4) {
        float a = g_p2[g_csrc[k]];
        float b = g_p2[g_csrc[k + 1]];
        float c = g_p2[g_csrc[k + 2]];
        float d = g_p2[g_csrc[k + 3]];
        s += (a + b) + (c + d);
    }
    for (; k < s1; k++) s += g_p2[g_csrc[k]];
    red_add_f32(&g_pool1[batch[i]], s * g_dis[i]);
}

// ------------- final: out[g] = pool1/cnt + c0 ; reset state ------------------
__global__ void k_final(float* __restrict__ out, int ng) {
    int i = blockIdx.x * blockDim.x + threadIdx.x;
    if (i < ng) {
        out[i] = g_pool1[i] / fmaxf(g_cnt[i], 1.0f) + g_c0;
        g_pool1[i] = 0.0f;   // reset for next replay
        g_cnt[i] = 0.0f;
    }
}

// ---------------------------------------------------------------------------
extern "C" void kernel_launch(void* const* d_in, const int* in_sizes, int n_in,
                              void* d_out, int out_size) {
    const float* x   = (const float*)d_in[0];
    const int* ei    = (const int*)d_in[1];
    const int* batch = (const int*)d_in[2];
    const float* W1 = (const float*)d_in[3];
    const float* b1 = (const float*)d_in[4];
    const float* W2 = (const float*)d_in[5];
    const float* b2 = (const float*)d_in[6];
    const float* W3 = (const float*)d_in[7];
    const float* b3 = (const float*)d_in[8];
    const float* lw = (const float*)d_in[9];
    const float* lb = (const float*)d_in[10];
    float* out = (float*)d_out;

    int n  = in_sizes[0] / 11;
    int e  = in_sizes[1] / 2;
    int ng = out_size;
    const int* src = ei;
    const int* dst = ei + e;

    int nb  = (n + 1023) / 1024;
    int sb  = (n + 127) / 128;          // staging blocks
    int fb4 = (e + 1023) / 1024;        // fill blocks (4 edges/thread)

    k_deg<<<fb4, 256>>>(dst, e, W3, b3, lw, lb);
    k_scanA<<<nb, 256>>>(n);
    k_scanC<<<nb, 256>>>(batch, n);
    k_stage_fill<<<sb + fb4, 256>>>(x, src, dst, n, e, sb);

    k_layer1<<<(n + 63) / 64, 256>>>(W1, b1, n);
    k_layer2<<<(n + 127) / 128, 256>>>(W2, b2, n);
    k_layer3<<<(n + 255) / 256, 256>>>(batch, n);
    k_final<<<(ng + 255) / 256, 256>>>(out, ng);
}